// round 1
// baseline (speedup 1.0000x reference)
#include <cuda_runtime.h>
#include <cuda_bf16.h>
#include <math.h>

// ---------------- Problem constants (B=1) ----------------
#define T_LEN   4096
#define DMODEL  2048
#define NHEAD   16
#define DHEAD   128
#define NCHUNK  64
#define CLEN    64
#define QKVZ_N  8192   // 2*kd + 2*vd
#define MIX_N   6144   // q+k+v channels
#define MDIM    8192

// ---------------- Scratch (device globals; no allocation allowed) ----------------
__device__ float g_h   [T_LEN * DMODEL];        // rmsnorm output (reused for h2)
__device__ float g_qkvz[T_LEN * QKVZ_N];        // qkvz GEMM out; later reused as gate/gu
__device__ float g_ba  [T_LEN * 32];
__device__ float g_qb  [NHEAD * T_LEN * DHEAD]; // l2norm(q)*scale, [H][T][128]
__device__ float g_kb  [NHEAD * T_LEN * DHEAD];
__device__ float g_vb  [NHEAD * T_LEN * DHEAD];
__device__ float g_beta[NHEAD * T_LEN];
__device__ float g_g   [NHEAD * T_LEN];
__device__ float g_gcs [NHEAD * T_LEN];         // within-chunk cumsum of g
__device__ float g_u   [NHEAD * T_LEN * DHEAD];
__device__ float g_wb  [NHEAD * T_LEN * DHEAD];
__device__ float g_attn[NHEAD * NCHUNK * CLEN * CLEN];
__device__ float g_o   [NHEAD * T_LEN * DHEAD];
__device__ float g_oc  [T_LEN * DMODEL];        // gated-norm output, [T][D]
__device__ float g_x2  [T_LEN * DMODEL];        // residual after attention
__device__ float g_up  [T_LEN * MDIM];

// ---------------- helpers ----------------
__device__ __forceinline__ float block_reduce_sum(float v, float* shm, int tid, int nthreads) {
    #pragma unroll
    for (int o = 16; o; o >>= 1) v += __shfl_down_sync(0xffffffffu, v, o);
    __syncthreads();                       // protect shm reuse across calls
    if ((tid & 31) == 0) shm[tid >> 5] = v;
    __syncthreads();
    int nw = nthreads >> 5;
    float s = (tid < nw) ? shm[tid] : 0.f;
    if (tid < 32) {
        #pragma unroll
        for (int o = 16; o; o >>= 1) s += __shfl_down_sync(0xffffffffu, s, o);
        if (tid == 0) shm[0] = s;
    }
    __syncthreads();
    return shm[0];
}

__device__ __forceinline__ float silu_f(float x) { return x / (1.f + __expf(-x)); }

// ---------------- RMSNorm (rows of 2048) ----------------
__global__ void rmsnorm_kernel(const float* __restrict__ x, const float* __restrict__ w,
                               float* __restrict__ y) {
    int t = blockIdx.x, tid = threadIdx.x;
    __shared__ float shm[32];
    const float* xr = x + (size_t)t * DMODEL;
    float ss = 0.f;
    for (int d = tid; d < DMODEL; d += 256) { float v = xr[d]; ss += v * v; }
    ss = block_reduce_sum(ss, shm, tid, 256);
    float inv = rsqrtf(ss / (float)DMODEL + 1e-5f);
    float* yr = y + (size_t)t * DMODEL;
    for (int d = tid; d < DMODEL; d += 256) yr[d] = xr[d] * inv * w[d];
}

// ---------------- SGEMM: C[M,N] = A[M,K] * B[N,K]^T (+R) ----------------
template <bool RES>
__global__ void __launch_bounds__(256) sgemm_nt(const float* __restrict__ A,
                                                const float* __restrict__ B,
                                                const float* __restrict__ R,
                                                float* __restrict__ C,
                                                int M, int N, int K) {
    __shared__ float As[8][128];
    __shared__ float Bs[8][128];
    int tid = threadIdx.x;
    int m0 = blockIdx.y * 128, n0 = blockIdx.x * 128;
    int lr = tid >> 1;
    int lc = (tid & 1) << 2;
    int ty = tid >> 4, tx = tid & 15;
    const float* Ap = A + (size_t)(m0 + lr) * K + lc;
    const float* Bp = B + (size_t)(n0 + lr) * K + lc;
    float acc[8][8];
    #pragma unroll
    for (int i = 0; i < 8; i++)
        #pragma unroll
        for (int j = 0; j < 8; j++) acc[i][j] = 0.f;

    for (int k0 = 0; k0 < K; k0 += 8) {
        float4 av = *(const float4*)(Ap + k0);
        float4 bv = *(const float4*)(Bp + k0);
        __syncthreads();
        As[lc + 0][lr] = av.x; As[lc + 1][lr] = av.y; As[lc + 2][lr] = av.z; As[lc + 3][lr] = av.w;
        Bs[lc + 0][lr] = bv.x; Bs[lc + 1][lr] = bv.y; Bs[lc + 2][lr] = bv.z; Bs[lc + 3][lr] = bv.w;
        __syncthreads();
        #pragma unroll
        for (int kk = 0; kk < 8; kk++) {
            float a[8], b[8];
            *(float4*)&a[0] = *(const float4*)&As[kk][ty * 8];
            *(float4*)&a[4] = *(const float4*)&As[kk][ty * 8 + 4];
            *(float4*)&b[0] = *(const float4*)&Bs[kk][tx * 8];
            *(float4*)&b[4] = *(const float4*)&Bs[kk][tx * 8 + 4];
            #pragma unroll
            for (int i = 0; i < 8; i++)
                #pragma unroll
                for (int j = 0; j < 8; j++) acc[i][j] += a[i] * b[j];
        }
    }
    #pragma unroll
    for (int i = 0; i < 8; i++) {
        int row = m0 + ty * 8 + i;
        float* Cp = C + (size_t)row * N + n0 + tx * 8;
        const float* Rp = R + (size_t)row * N + n0 + tx * 8;
        #pragma unroll
        for (int j = 0; j < 8; j += 4) {
            float4 v;
            v.x = acc[i][j]; v.y = acc[i][j + 1]; v.z = acc[i][j + 2]; v.w = acc[i][j + 3];
            if (RES) {
                float4 r = *(const float4*)(Rp + j);
                v.x += r.x; v.y += r.y; v.z += r.z; v.w += r.w;
            }
            *(float4*)(Cp + j) = v;
        }
    }
}

// ---------------- small-N GEMM for ba: C[4096,32] = A*B^T ----------------
__global__ void gemm_n32(const float* __restrict__ A, const float* __restrict__ B,
                         float* __restrict__ C, int K) {
    __shared__ float hs[32][65];
    __shared__ float ws[32][65];
    int m0 = blockIdx.x * 32;
    int tid = threadIdx.x;
    int c = tid & 31, r0 = tid >> 5;
    float acc[4] = {0, 0, 0, 0};
    for (int k0 = 0; k0 < K; k0 += 64) {
        __syncthreads();
        for (int idx = tid; idx < 2048; idx += 256) {
            int r = idx >> 6, kk = idx & 63;
            hs[r][kk] = A[(size_t)(m0 + r) * K + k0 + kk];
            ws[r][kk] = B[(size_t)r * K + k0 + kk];
        }
        __syncthreads();
        for (int kk = 0; kk < 64; kk++) {
            float wv = ws[c][kk];
            #pragma unroll
            for (int s = 0; s < 4; s++) acc[s] += hs[r0 + 8 * s][kk] * wv;
        }
    }
    #pragma unroll
    for (int s = 0; s < 4; s++) C[(size_t)(m0 + r0 + 8 * s) * 32 + c] = acc[s];
}

// ---------------- causal conv + silu + l2norm + head split ----------------
__global__ void conv_kernel(const float* __restrict__ qkvz, const float* __restrict__ conv_w,
                            float* __restrict__ qo, float* __restrict__ ko, float* __restrict__ vo) {
    int t = blockIdx.y;
    int wh = blockIdx.x;            // which*16 + head
    int which = wh >> 4, head = wh & 15;
    int d = threadIdx.x;            // 0..127
    int c = which * 2048 + head * 128 + d;
    float acc = 0.f;
    #pragma unroll
    for (int j = 0; j < 4; j++) {
        int tt = t - 3 + j;
        if (tt >= 0) acc += qkvz[(size_t)tt * QKVZ_N + c] * conv_w[c * 4 + j];
    }
    float s = silu_f(acc);
    size_t oidx = ((size_t)head * T_LEN + t) * DHEAD + d;
    if (which == 2) { vo[oidx] = s; return; }
    __shared__ float shm[32];
    float ss = block_reduce_sum(s * s, shm, d, 128);
    float val = s * rsqrtf(ss + 1e-6f);
    if (which == 0) val *= 0.08838834764831845f;   // Dk^-0.5
    (which == 0 ? qo : ko)[oidx] = val;
}

// ---------------- beta / g ----------------
__global__ void betag_kernel(const float* __restrict__ ba, const float* __restrict__ A_log,
                             const float* __restrict__ dt_bias,
                             float* __restrict__ beta, float* __restrict__ g) {
    int idx = blockIdx.x * blockDim.x + threadIdx.x;
    if (idx >= NHEAD * T_LEN) return;
    int t = idx >> 4, h = idx & 15;
    float b = ba[t * 32 + h];
    float a = ba[t * 32 + 16 + h];
    beta[h * T_LEN + t] = 1.f / (1.f + expf(-b));
    float xx = a + dt_bias[h];
    float sp = (xx > 20.f) ? xx : log1pf(expf(xx));
    g[h * T_LEN + t] = -expf(A_log[h]) * sp;
}

// ---------------- within-chunk cumsum of g ----------------
__global__ void gcs_kernel(const float* __restrict__ g, float* __restrict__ gcs) {
    int h = blockIdx.x >> 6, n = blockIdx.x & 63;
    __shared__ float s[64];
    int i = threadIdx.x;
    int base = h * T_LEN + n * 64;
    s[i] = g[base + i];
    __syncthreads();
    for (int off = 1; off < 64; off <<= 1) {
        float v = (i >= off) ? s[i - off] : 0.f;
        __syncthreads();
        s[i] += v;
        __syncthreads();
    }
    gcs[base + i] = s[i];
}

// ---------------- per-chunk prep: A, T=(I+A)^-1, u, w, attn ----------------
struct PrepShm {
    float k[64][128];
    float x[64][128];   // v*beta, later q
    float A[64][64];
    float T[64][64];
    float gcs[64];
    float beta[64];
    float coef[64];
};

extern __shared__ float dyn_smem[];

__global__ void __launch_bounds__(128) prep_kernel(
    const float* __restrict__ gk, const float* __restrict__ gv, const float* __restrict__ gq,
    const float* __restrict__ gbeta, const float* __restrict__ ggcs,
    float* __restrict__ gu, float* __restrict__ gw, float* __restrict__ gattn) {
    PrepShm& S = *(PrepShm*)dyn_smem;
    int n = blockIdx.x, h = blockIdx.y;
    int tid = threadIdx.x;
    int base = h * T_LEN + n * 64;

    if (tid < 64) {
        S.gcs[tid]  = ggcs[base + tid];
        S.beta[tid] = gbeta[base + tid];
    }
    for (int idx = tid; idx < 64 * 128; idx += 128) {
        int i = idx >> 7, d = idx & 127;
        S.k[i][d] = gk[(size_t)(base + i) * DHEAD + d];
    }
    __syncthreads();
    for (int idx = tid; idx < 64 * 128; idx += 128) {
        int i = idx >> 7, d = idx & 127;
        S.x[i][d] = gv[(size_t)(base + i) * DHEAD + d] * S.beta[i];
    }
    // A[i][j] = beta_i * <k_i,k_j> * exp(gcs_i - gcs_j), j<i (strict)
    for (int idx = tid; idx < 4096; idx += 128) {
        int i = idx >> 6, j = idx & 63;
        float val = 0.f;
        if (j < i) {
            float acc = 0.f;
            #pragma unroll 8
            for (int d = 0; d < 128; d++) {
                int dd = (d + tid) & 127;   // lane rotation: conflict-free
                acc += S.k[i][dd] * S.k[j][dd];
            }
            val = acc * S.beta[i] * __expf(S.gcs[i] - S.gcs[j]);
        }
        S.A[i][j] = val;
    }
    __syncthreads();
    // forward substitution: T = (I+A)^-1
    if (tid < 64) S.T[0][tid] = (tid == 0) ? 1.f : 0.f;
    __syncthreads();
    for (int i = 1; i < 64; i++) {
        if (tid < 64) {
            float acc = 0.f;
            for (int j = 0; j < i; j++) acc += S.A[i][j] * S.T[j][tid];
            S.T[i][tid] = ((tid == i) ? 1.f : 0.f) - acc;
        }
        __syncthreads();
    }
    if (tid < 64) S.coef[tid] = S.beta[tid] * __expf(S.gcs[tid]);
    __syncthreads();
    // u = T @ (v*beta), w = T @ (k*beta*exp(gcs))
    for (int idx = tid; idx < 64 * 128; idx += 128) {
        int i = idx >> 7, d = idx & 127;
        float au = 0.f, aw = 0.f;
        for (int j = 0; j <= i; j++) {
            float tij = S.T[i][j];
            au += tij * S.x[j][d];
            aw += tij * S.coef[j] * S.k[j][d];
        }
        gu[(size_t)(base + i) * DHEAD + d] = au;
        gw[(size_t)(base + i) * DHEAD + d] = aw;
    }
    __syncthreads();
    for (int idx = tid; idx < 64 * 128; idx += 128) {
        int i = idx >> 7, d = idx & 127;
        S.x[i][d] = gq[(size_t)(base + i) * DHEAD + d];
    }
    __syncthreads();
    // attn[i][j] = <q_i,k_j> * exp(gcs_i - gcs_j), j<=i
    float* attn_out = gattn + ((size_t)(h * 64 + n)) * 64 * 64;
    for (int idx = tid; idx < 4096; idx += 128) {
        int i = idx >> 6, j = idx & 63;
        float val = 0.f;
        if (j <= i) {
            float acc = 0.f;
            #pragma unroll 8
            for (int d = 0; d < 128; d++) {
                int dd = (d + tid) & 127;
                acc += S.x[i][dd] * S.k[j][dd];
            }
            val = acc * __expf(S.gcs[i] - S.gcs[j]);
        }
        attn_out[i * 64 + j] = val;
    }
}

// ---------------- sequential scan over chunks, parallel over (head, dv-slice) ----------------
#define DVS 16
struct ScanShm {
    float S[128][DVS];
    float w[64][132];
    float q[64][132];
    float k[64][132];
    float attn[64][68];
    float u[64][DVS];
    float vn[64][DVS];
    float gcs[64];
    float ex[64];
};

__global__ void __launch_bounds__(256) scan_kernel(
    const float* __restrict__ gq, const float* __restrict__ gk, const float* __restrict__ gw,
    const float* __restrict__ gu, const float* __restrict__ gattn, const float* __restrict__ ggcs,
    float* __restrict__ go) {
    ScanShm& S = *(ScanShm*)dyn_smem;
    int h = blockIdx.x;
    int dv0 = blockIdx.y * DVS;
    int tid = threadIdx.x;

    for (int idx = tid; idx < 128 * DVS; idx += 256) S.S[idx >> 4][idx & 15] = 0.f;

    for (int n = 0; n < NCHUNK; n++) {
        int base = h * T_LEN + n * 64;
        if (tid < 64) S.gcs[tid] = ggcs[base + tid];
        for (int idx = tid; idx < 64 * 128; idx += 256) {
            int i = idx >> 7, d = idx & 127;
            size_t gidx = (size_t)(base + i) * DHEAD + d;
            S.w[i][d] = gw[gidx];
            S.q[i][d] = gq[gidx];
            S.k[i][d] = gk[gidx];
        }
        const float* ap = gattn + ((size_t)(h * 64 + n)) * 64 * 64;
        for (int idx = tid; idx < 4096; idx += 256) S.attn[idx >> 6][idx & 63] = ap[idx];
        for (int idx = tid; idx < 64 * DVS; idx += 256) {
            int i = idx >> 4, dv = idx & 15;
            S.u[i][dv] = gu[(size_t)(base + i) * DHEAD + dv0 + dv];
        }
        __syncthreads();
        if (tid < 64) S.ex[tid] = __expf(S.gcs[63] - S.gcs[tid]);

        // v_new = u - w @ S   (thread: i = tid/4, dv quad = (tid%4)*4)
        int i = tid >> 2, dvb = (tid & 3) * 4;
        {
            float4 uv = *(const float4*)&S.u[i][dvb];
            float a0 = uv.x, a1 = uv.y, a2 = uv.z, a3 = uv.w;
            for (int d = 0; d < 128; d++) {
                float wv = S.w[i][d];
                float4 sv = *(const float4*)&S.S[d][dvb];
                a0 -= wv * sv.x; a1 -= wv * sv.y; a2 -= wv * sv.z; a3 -= wv * sv.w;
            }
            float4 r; r.x = a0; r.y = a1; r.z = a2; r.w = a3;
            *(float4*)&S.vn[i][dvb] = r;
        }
        __syncthreads();
        // o = exp(gcs_i) * q_i @ S + attn_i @ v_new
        {
            float a0 = 0, a1 = 0, a2 = 0, a3 = 0;
            for (int d = 0; d < 128; d++) {
                float qv = S.q[i][d];
                float4 sv = *(const float4*)&S.S[d][dvb];
                a0 += qv * sv.x; a1 += qv * sv.y; a2 += qv * sv.z; a3 += qv * sv.w;
            }
            float eg = __expf(S.gcs[i]);
            a0 *= eg; a1 *= eg; a2 *= eg; a3 *= eg;
            for (int j = 0; j <= i; j++) {
                float av = S.attn[i][j];
                float4 vv = *(const float4*)&S.vn[j][dvb];
                a0 += av * vv.x; a1 += av * vv.y; a2 += av * vv.z; a3 += av * vv.w;
            }
            float4 r; r.x = a0; r.y = a1; r.z = a2; r.w = a3;
            *(float4*)(go + (size_t)(base + i) * DHEAD + dv0 + dvb) = r;
        }
        __syncthreads();
        // S = S * exp(g_last) + k_dec^T @ v_new
        {
            float gle = __expf(S.gcs[63]);
            #pragma unroll
            for (int r = 0; r < 2; r++) {
                int qi = tid + 256 * r;
                int d = qi >> 2, db = (qi & 3) * 4;
                float4 sv = *(const float4*)&S.S[d][db];
                float a0 = sv.x * gle, a1 = sv.y * gle, a2 = sv.z * gle, a3 = sv.w * gle;
                for (int ii = 0; ii < 64; ii++) {
                    float kk = S.k[ii][d] * S.ex[ii];
                    float4 vv = *(const float4*)&S.vn[ii][db];
                    a0 += kk * vv.x; a1 += kk * vv.y; a2 += kk * vv.z; a3 += kk * vv.w;
                }
                float4 w4; w4.x = a0; w4.y = a1; w4.z = a2; w4.w = a3;
                *(float4*)&S.S[d][db] = w4;
            }
        }
        __syncthreads();
    }
}

// ---------------- gated RMSNorm * silu(z), merge heads ----------------
__global__ void gated_out_kernel(const float* __restrict__ go, const float* __restrict__ qkvz,
                                 const float* __restrict__ onw, float* __restrict__ oc) {
    int h = blockIdx.x, t = blockIdx.y, d = threadIdx.x;
    __shared__ float shm[32];
    float v = go[((size_t)h * T_LEN + t) * DHEAD + d];
    float ss = block_reduce_sum(v * v, shm, d, 128);
    float inv = rsqrtf(ss / 128.f + 1e-5f);
    float z = qkvz[(size_t)t * QKVZ_N + MIX_N + h * 128 + d];
    oc[(size_t)t * DMODEL + h * 128 + d] = v * inv * onw[d] * silu_f(z);
}

// ---------------- GLU: gate = silu(gate) * up ----------------
__global__ void glu_kernel(float* __restrict__ gate, const float* __restrict__ up) {
    int i = blockIdx.x * blockDim.x + threadIdx.x;
    float gv = gate[i];
    gate[i] = silu_f(gv) * up[i];
}

// ---------------- host launch ----------------
extern "C" void kernel_launch(void* const* d_in, const int* in_sizes, int n_in,
                              void* d_out, int out_size) {
    const float* x       = (const float*)d_in[0];
    const float* ln1_w   = (const float*)d_in[2];
    const float* qkvz_w  = (const float*)d_in[3];
    const float* ba_w    = (const float*)d_in[4];
    const float* conv_w  = (const float*)d_in[5];
    const float* A_log   = (const float*)d_in[6];
    const float* dt_bias = (const float*)d_in[7];
    const float* o_norm_w= (const float*)d_in[8];
    const float* out_w   = (const float*)d_in[9];
    const float* ln2_w   = (const float*)d_in[10];
    const float* gate_w  = (const float*)d_in[11];
    const float* up_w    = (const float*)d_in[12];
    const float* down_w  = (const float*)d_in[13];
    float* out = (float*)d_out;

    float *h, *qkvz, *ba, *qb, *kb, *vb, *beta, *gg, *gcs, *u, *w, *attn, *o, *oc, *x2, *up;
    cudaGetSymbolAddress((void**)&h,    g_h);
    cudaGetSymbolAddress((void**)&qkvz, g_qkvz);
    cudaGetSymbolAddress((void**)&ba,   g_ba);
    cudaGetSymbolAddress((void**)&qb,   g_qb);
    cudaGetSymbolAddress((void**)&kb,   g_kb);
    cudaGetSymbolAddress((void**)&vb,   g_vb);
    cudaGetSymbolAddress((void**)&beta, g_beta);
    cudaGetSymbolAddress((void**)&gg,   g_g);
    cudaGetSymbolAddress((void**)&gcs,  g_gcs);
    cudaGetSymbolAddress((void**)&u,    g_u);
    cudaGetSymbolAddress((void**)&w,    g_wb);
    cudaGetSymbolAddress((void**)&attn, g_attn);
    cudaGetSymbolAddress((void**)&o,    g_o);
    cudaGetSymbolAddress((void**)&oc,   g_oc);
    cudaGetSymbolAddress((void**)&x2,   g_x2);
    cudaGetSymbolAddress((void**)&up,   g_up);

    cudaFuncSetAttribute(prep_kernel, cudaFuncAttributeMaxDynamicSharedMemorySize, (int)sizeof(PrepShm));
    cudaFuncSetAttribute(scan_kernel, cudaFuncAttributeMaxDynamicSharedMemorySize, (int)sizeof(ScanShm));

    // 1) h = rms(x, ln1)
    rmsnorm_kernel<<<T_LEN, 256>>>(x, ln1_w, h);
    // 2) qkvz = h @ qkvz_w^T ; ba = h @ ba_w^T
    sgemm_nt<false><<<dim3(QKVZ_N / 128, T_LEN / 128), 256>>>(h, qkvz_w, nullptr, qkvz, T_LEN, QKVZ_N, DMODEL);
    gemm_n32<<<T_LEN / 32, 256>>>(h, ba_w, ba, DMODEL);
    // 3) conv + silu + l2norm + split heads
    conv_kernel<<<dim3(48, T_LEN), 128>>>(qkvz, conv_w, qb, kb, vb);
    // 4) beta, g, gcs
    betag_kernel<<<(NHEAD * T_LEN + 255) / 256, 256>>>(ba, A_log, dt_bias, beta, gg);
    gcs_kernel<<<NHEAD * NCHUNK, 64>>>(gg, gcs);
    // 5) chunk prep
    prep_kernel<<<dim3(NCHUNK, NHEAD), 128, sizeof(PrepShm)>>>(kb, vb, qb, beta, gcs, u, w, attn);
    // 6) scan
    scan_kernel<<<dim3(NHEAD, DHEAD / DVS), 256, sizeof(ScanShm)>>>(qb, kb, w, u, attn, gcs, o);
    // 7) gated norm * silu(z)
    gated_out_kernel<<<dim3(NHEAD, T_LEN), 128>>>(o, qkvz, o_norm_w, oc);
    // 8) x2 = x + oc @ out_w^T
    sgemm_nt<true><<<dim3(DMODEL / 128, T_LEN / 128), 256>>>(oc, out_w, x, x2, T_LEN, DMODEL, DMODEL);
    // 9) h2 = rms(x2, ln2)
    rmsnorm_kernel<<<T_LEN, 256>>>(x2, ln2_w, h);
    // 10) gate, up GEMMs
    sgemm_nt<false><<<dim3(MDIM / 128, T_LEN / 128), 256>>>(h, gate_w, nullptr, qkvz, T_LEN, MDIM, DMODEL);
    sgemm_nt<false><<<dim3(MDIM / 128, T_LEN / 128), 256>>>(h, up_w, nullptr, up, T_LEN, MDIM, DMODEL);
    // 11) gu = silu(gate) * up  (in place in qkvz)
    glu_kernel<<<(T_LEN * MDIM) / 256, 256>>>(qkvz, up);
    // 12) out = x2 + gu @ down_w^T
    sgemm_nt<true><<<dim3(DMODEL / 128, T_LEN / 128), 256>>>(qkvz, down_w, x2, out, T_LEN, DMODEL, MDIM);
}

// round 6
// speedup vs baseline: 2.0576x; 2.0576x over previous
#include <cuda_runtime.h>
#include <cuda_bf16.h>
#include <math.h>
#include <stdint.h>

// ---------------- Problem constants (B=1) ----------------
#define T_LEN   4096
#define DMODEL  2048
#define NHEAD   16
#define DHEAD   128
#define NCHUNK  64
#define CLEN    64
#define QKVZ_N  8192   // 2*kd + 2*vd
#define MIX_N   6144   // q+k+v channels
#define MDIM    8192

// ---------------- fp32 scratch ----------------
__device__ float g_h   [T_LEN * DMODEL];
__device__ float g_qkvz[T_LEN * QKVZ_N];
__device__ float g_ba  [T_LEN * 32];
__device__ float g_qb  [NHEAD * T_LEN * DHEAD];
__device__ float g_kb  [NHEAD * T_LEN * DHEAD];
__device__ float g_vb  [NHEAD * T_LEN * DHEAD];
__device__ float g_beta[NHEAD * T_LEN];
__device__ float g_g   [NHEAD * T_LEN];
__device__ float g_gcs [NHEAD * T_LEN];
__device__ float g_u   [NHEAD * T_LEN * DHEAD];
__device__ float g_wb  [NHEAD * T_LEN * DHEAD];
__device__ float g_attn[NHEAD * NCHUNK * CLEN * CLEN];
__device__ float g_o   [NHEAD * T_LEN * DHEAD];
__device__ float g_x2  [T_LEN * DMODEL];
__device__ float g_up  [T_LEN * MDIM];

// ---------------- bf16 hi/lo scratch ----------------
__device__ __nv_bfloat16 b_h_hi [T_LEN * DMODEL];
__device__ __nv_bfloat16 b_h_lo [T_LEN * DMODEL];
__device__ __nv_bfloat16 b_oc_hi[T_LEN * DMODEL];
__device__ __nv_bfloat16 b_oc_lo[T_LEN * DMODEL];
__device__ __nv_bfloat16 b_gu_hi[T_LEN * MDIM];
__device__ __nv_bfloat16 b_gu_lo[T_LEN * MDIM];
__device__ __nv_bfloat16 b_w1_hi[QKVZ_N * DMODEL];
__device__ __nv_bfloat16 b_w1_lo[QKVZ_N * DMODEL];
__device__ __nv_bfloat16 b_wo_hi[DMODEL * DMODEL];
__device__ __nv_bfloat16 b_wo_lo[DMODEL * DMODEL];
__device__ __nv_bfloat16 b_wg_hi[MDIM * DMODEL];
__device__ __nv_bfloat16 b_wg_lo[MDIM * DMODEL];
__device__ __nv_bfloat16 b_wu_hi[MDIM * DMODEL];
__device__ __nv_bfloat16 b_wu_lo[MDIM * DMODEL];
__device__ __nv_bfloat16 b_wd_hi[DMODEL * MDIM];
__device__ __nv_bfloat16 b_wd_lo[DMODEL * MDIM];

// ---------------- PTX helpers (sm_103-safe: cp.async / ldmatrix / mma.sync only) ----------------
__device__ __forceinline__ uint32_t smem_u32(const void* p) {
    uint32_t a;
    asm("{ .reg .u64 t; cvta.to.shared.u64 t, %1; cvt.u32.u64 %0, t; }" : "=r"(a) : "l"(p));
    return a;
}
#define CP_ASYNC16(d,s) asm volatile("cp.async.cg.shared.global [%0], [%1], 16;" :: "r"(d), "l"(s))
#define CP_COMMIT()     asm volatile("cp.async.commit_group;" ::: "memory")
#define CP_WAIT2()      asm volatile("cp.async.wait_group 2;" ::: "memory")
#define CP_WAIT1()      asm volatile("cp.async.wait_group 1;" ::: "memory")
#define CP_WAIT0()      asm volatile("cp.async.wait_group 0;" ::: "memory")

// ldmatrix x4: outputs through local scalars (frontend-safe), stored via pointer
__device__ __forceinline__ void ldsm4(uint32_t addr, uint32_t* o) {
    uint32_t r0, r1, r2, r3;
    asm volatile("ldmatrix.sync.aligned.m8n8.x4.shared.b16 {%0,%1,%2,%3}, [%4];"
        : "=r"(r0), "=r"(r1), "=r"(r2), "=r"(r3) : "r"(addr));
    o[0] = r0; o[1] = r1; o[2] = r2; o[3] = r3;
}

// bf16 m16n8k16 mma, fp32 accum; scalar temps for asm operands
__device__ __forceinline__ void mma16816(float* d, uint32_t a0, uint32_t a1, uint32_t a2,
                                         uint32_t a3, uint32_t b0, uint32_t b1) {
    float t0 = d[0], t1 = d[1], t2 = d[2], t3 = d[3];
    asm volatile("mma.sync.aligned.m16n8k16.row.col.f32.bf16.bf16.f32 "
        "{%0,%1,%2,%3},{%4,%5,%6,%7},{%8,%9},{%0,%1,%2,%3};"
        : "+f"(t0), "+f"(t1), "+f"(t2), "+f"(t3)
        : "r"(a0), "r"(a1), "r"(a2), "r"(a3), "r"(b0), "r"(b1));
    d[0] = t0; d[1] = t1; d[2] = t2; d[3] = t3;
}

// ---------------- helpers ----------------
__device__ __forceinline__ float block_reduce_sum(float v, float* shm, int tid, int nthreads) {
    #pragma unroll
    for (int o = 16; o; o >>= 1) v += __shfl_down_sync(0xffffffffu, v, o);
    __syncthreads();
    if ((tid & 31) == 0) shm[tid >> 5] = v;
    __syncthreads();
    int nw = nthreads >> 5;
    float s = (tid < nw) ? shm[tid] : 0.f;
    if (tid < 32) {
        #pragma unroll
        for (int o = 16; o; o >>= 1) s += __shfl_down_sync(0xffffffffu, s, o);
        if (tid == 0) shm[0] = s;
    }
    __syncthreads();
    return shm[0];
}
__device__ __forceinline__ float silu_f(float x) { return x / (1.f + __expf(-x)); }
__device__ __forceinline__ void split_hilo(float x, __nv_bfloat16& h, __nv_bfloat16& l) {
    h = __float2bfloat16(x);
    l = __float2bfloat16(x - __bfloat162float(h));
}

// ---------------- weight fp32 -> bf16 hi/lo ----------------
__global__ void cvt_hilo(const float* __restrict__ x, __nv_bfloat16* __restrict__ hi,
                         __nv_bfloat16* __restrict__ lo, int n) {
    int i = (blockIdx.x * blockDim.x + threadIdx.x) * 4;
    if (i >= n) return;
    float4 v = *(const float4*)(x + i);
    __nv_bfloat16 h0, h1, h2, h3, l0, l1, l2, l3;
    split_hilo(v.x, h0, l0); split_hilo(v.y, h1, l1);
    split_hilo(v.z, h2, l2); split_hilo(v.w, h3, l3);
    __nv_bfloat162* hp = (__nv_bfloat162*)(hi + i);
    __nv_bfloat162* lp = (__nv_bfloat162*)(lo + i);
    hp[0] = __nv_bfloat162(h0, h1); hp[1] = __nv_bfloat162(h2, h3);
    lp[0] = __nv_bfloat162(l0, l1); lp[1] = __nv_bfloat162(l2, l3);
}

// ---------------- RMSNorm + hi/lo ----------------
__global__ void rmsnorm_kernel(const float* __restrict__ x, const float* __restrict__ w,
                               float* __restrict__ y, __nv_bfloat16* __restrict__ yhi,
                               __nv_bfloat16* __restrict__ ylo) {
    int t = blockIdx.x, tid = threadIdx.x;
    __shared__ float shm[32];
    const float* xr = x + (size_t)t * DMODEL;
    float ss = 0.f;
    for (int d = tid; d < DMODEL; d += 256) { float v = xr[d]; ss += v * v; }
    ss = block_reduce_sum(ss, shm, tid, 256);
    float inv = rsqrtf(ss / (float)DMODEL + 1e-5f);
    for (int d = tid; d < DMODEL; d += 256) {
        float v = xr[d] * inv * w[d];
        y[(size_t)t * DMODEL + d] = v;
        __nv_bfloat16 h, l; split_hilo(v, h, l);
        yhi[(size_t)t * DMODEL + d] = h;
        ylo[(size_t)t * DMODEL + d] = l;
    }
}

// ---------------- HMMA GEMM: C[M,N] = A[M,K] @ B[N,K]^T (+R if R!=null) ----------------
// 3-term bf16 split accumulated in fp32 registers across passes (Ahi,Bhi),(Alo,Bhi),(Ahi,Blo).
// 128x128 tile, BK=32, 8 warps (4x2), warp tile 32x64, cp.async 4-stage pipeline.
// Smem row = 32 bf16 = 64B, chunk swizzle c ^= (row>>1)&3 -> conflict-free ldmatrix phases.
#define GSTAGE 16384   // A 8KB + B 8KB
__global__ void __launch_bounds__(256) gemm_tc(
    const __nv_bfloat16* __restrict__ Ahi, const __nv_bfloat16* __restrict__ Alo,
    const __nv_bfloat16* __restrict__ Bhi, const __nv_bfloat16* __restrict__ Blo,
    const float* __restrict__ R, float* __restrict__ C, int M, int N, int K) {
    extern __shared__ char smem_raw[];
    uint32_t sbase = smem_u32(smem_raw);
    int tid = threadIdx.x, lane = tid & 31, warp = tid >> 5;
    int wm = warp >> 1, wn = warp & 1;
    int m0 = blockIdx.y * 128, n0 = blockIdx.x * 128;
    const int KT = K >> 5;
    const int total = 3 * KT;

    float acc[2][8][4];
    #pragma unroll
    for (int a = 0; a < 2; a++)
        #pragma unroll
        for (int b = 0; b < 8; b++)
            #pragma unroll
            for (int c = 0; c < 4; c++) acc[a][b][c] = 0.f;

    // per-lane ldmatrix offsets (stage-relative), both k-steps
    uint32_t aoff[2][2], boff[4][2];
    {
        int mat = lane >> 3, r = lane & 7;
        #pragma unroll
        for (int mt = 0; mt < 2; mt++) {
            int row = wm * 32 + mt * 16 + ((mat & 1) << 3) + r;
            #pragma unroll
            for (int ks = 0; ks < 2; ks++) {
                int ch = (ks << 1) + (mat >> 1);
                aoff[mt][ks] = row * 64 + ((ch ^ ((row >> 1) & 3)) << 4);
            }
        }
        #pragma unroll
        for (int j = 0; j < 4; j++) {
            int row = wn * 64 + j * 16 + ((mat >> 1) << 3) + r;
            #pragma unroll
            for (int ks = 0; ks < 2; ks++) {
                int ch = (ks << 1) + (mat & 1);
                boff[j][ks] = 8192 + row * 64 + ((ch ^ ((row >> 1) & 3)) << 4);
            }
        }
    }

    // cp.async stage loader: this thread's 2 A-chunks + 2 B-chunks (16B each)
    int lrow[2], lc[2]; uint32_t lso[2];
    #pragma unroll
    for (int i = 0; i < 2; i++) {
        int id = (tid << 1) | i;
        lrow[i] = id >> 2; lc[i] = id & 3;
        lso[i] = lrow[i] * 64 + ((lc[i] ^ ((lrow[i] >> 1) & 3)) << 4);
    }

    auto load_stage = [&](int st) {
        int buf = st & 3;
        int p = st / KT;
        int k0 = (st - p * KT) << 5;
        const __nv_bfloat16* Ap = (p == 1) ? Alo : Ahi;
        const __nv_bfloat16* Bp = (p == 2) ? Blo : Bhi;
        uint32_t ab = sbase + buf * GSTAGE;
        uint32_t bb = ab + 8192;
        #pragma unroll
        for (int i = 0; i < 2; i++) {
            CP_ASYNC16(ab + lso[i], Ap + (size_t)(m0 + lrow[i]) * K + k0 + lc[i] * 8);
            CP_ASYNC16(bb + lso[i], Bp + (size_t)(n0 + lrow[i]) * K + k0 + lc[i] * 8);
        }
        CP_COMMIT();
    };

    load_stage(0); load_stage(1); load_stage(2);

    for (int st = 0; st < total; st++) {
        int rem = total - 1 - st;
        if (rem >= 2) { CP_WAIT2(); } else if (rem == 1) { CP_WAIT1(); } else { CP_WAIT0(); }
        __syncthreads();
        if (st + 3 < total) load_stage(st + 3);

        uint32_t stb = sbase + (st & 3) * GSTAGE;
        #pragma unroll
        for (int ks = 0; ks < 2; ks++) {
            uint32_t af[2][4], bf[4][4];
            ldsm4(stb + aoff[0][ks], af[0]);
            ldsm4(stb + aoff[1][ks], af[1]);
            #pragma unroll
            for (int j = 0; j < 4; j++) ldsm4(stb + boff[j][ks], bf[j]);
            #pragma unroll
            for (int mt = 0; mt < 2; mt++) {
                #pragma unroll
                for (int j = 0; j < 4; j++) {
                    mma16816(&acc[mt][2 * j][0],     af[mt][0], af[mt][1], af[mt][2], af[mt][3], bf[j][0], bf[j][1]);
                    mma16816(&acc[mt][2 * j + 1][0], af[mt][0], af[mt][1], af[mt][2], af[mt][3], bf[j][2], bf[j][3]);
                }
            }
        }
    }

    // epilogue
    #pragma unroll
    for (int mt = 0; mt < 2; mt++) {
        #pragma unroll
        for (int nt = 0; nt < 8; nt++) {
            int rr = m0 + wm * 32 + mt * 16 + (lane >> 2);
            int cc = n0 + wn * 64 + nt * 8 + ((lane & 3) << 1);
            float2 v0, v1;
            v0.x = acc[mt][nt][0]; v0.y = acc[mt][nt][1];
            v1.x = acc[mt][nt][2]; v1.y = acc[mt][nt][3];
            if (R != 0) {
                const float2 r0 = *(const float2*)(R + (size_t)rr * N + cc);
                const float2 r1 = *(const float2*)(R + (size_t)(rr + 8) * N + cc);
                v0.x += r0.x; v0.y += r0.y; v1.x += r1.x; v1.y += r1.y;
            }
            *(float2*)(C + (size_t)rr * N + cc) = v0;
            *(float2*)(C + (size_t)(rr + 8) * N + cc) = v1;
        }
    }
}

// ---------------- small-N GEMM for ba ----------------
__global__ void gemm_n32(const float* __restrict__ A, const float* __restrict__ B,
                         float* __restrict__ C, int K) {
    __shared__ float hs[32][65];
    __shared__ float ws[32][65];
    int m0 = blockIdx.x * 32;
    int tid = threadIdx.x;
    int c = tid & 31, r0 = tid >> 5;
    float acc[4] = {0, 0, 0, 0};
    for (int k0 = 0; k0 < K; k0 += 64) {
        __syncthreads();
        for (int idx = tid; idx < 2048; idx += 256) {
            int r = idx >> 6, kk = idx & 63;
            hs[r][kk] = A[(size_t)(m0 + r) * K + k0 + kk];
            ws[r][kk] = B[(size_t)r * K + k0 + kk];
        }
        __syncthreads();
        for (int kk = 0; kk < 64; kk++) {
            float wv = ws[c][kk];
            #pragma unroll
            for (int s = 0; s < 4; s++) acc[s] += hs[r0 + 8 * s][kk] * wv;
        }
    }
    #pragma unroll
    for (int s = 0; s < 4; s++) C[(size_t)(m0 + r0 + 8 * s) * 32 + c] = acc[s];
}

// ---------------- causal conv + silu + l2norm + head split ----------------
__global__ void conv_kernel(const float* __restrict__ qkvz, const float* __restrict__ conv_w,
                            float* __restrict__ qo, float* __restrict__ ko, float* __restrict__ vo) {
    int t = blockIdx.y;
    int wh = blockIdx.x;
    int which = wh >> 4, head = wh & 15;
    int d = threadIdx.x;
    int c = which * 2048 + head * 128 + d;
    float acc = 0.f;
    #pragma unroll
    for (int j = 0; j < 4; j++) {
        int tt = t - 3 + j;
        if (tt >= 0) acc += qkvz[(size_t)tt * QKVZ_N + c] * conv_w[c * 4 + j];
    }
    float s = silu_f(acc);
    size_t oidx = ((size_t)head * T_LEN + t) * DHEAD + d;
    if (which == 2) { vo[oidx] = s; return; }
    __shared__ float shm[32];
    float ss = block_reduce_sum(s * s, shm, d, 128);
    float val = s * rsqrtf(ss + 1e-6f);
    if (which == 0) val *= 0.08838834764831845f;
    (which == 0 ? qo : ko)[oidx] = val;
}

// ---------------- beta / g ----------------
__global__ void betag_kernel(const float* __restrict__ ba, const float* __restrict__ A_log,
                             const float* __restrict__ dt_bias,
                             float* __restrict__ beta, float* __restrict__ g) {
    int idx = blockIdx.x * blockDim.x + threadIdx.x;
    if (idx >= NHEAD * T_LEN) return;
    int t = idx >> 4, h = idx & 15;
    float b = ba[t * 32 + h];
    float a = ba[t * 32 + 16 + h];
    beta[h * T_LEN + t] = 1.f / (1.f + expf(-b));
    float xx = a + dt_bias[h];
    float sp = (xx > 20.f) ? xx : log1pf(expf(xx));
    g[h * T_LEN + t] = -expf(A_log[h]) * sp;
}

// ---------------- within-chunk cumsum of g ----------------
__global__ void gcs_kernel(const float* __restrict__ g, float* __restrict__ gcs) {
    int h = blockIdx.x >> 6, n = blockIdx.x & 63;
    __shared__ float s[64];
    int i = threadIdx.x;
    int base = h * T_LEN + n * 64;
    s[i] = g[base + i];
    __syncthreads();
    for (int off = 1; off < 64; off <<= 1) {
        float v = (i >= off) ? s[i - off] : 0.f;
        __syncthreads();
        s[i] += v;
        __syncthreads();
    }
    gcs[base + i] = s[i];
}

// ---------------- per-chunk prep: A, T=(I+A)^-1, u, w, attn ----------------
struct PrepShm {
    float k[64][128];
    float x[64][128];
    float A[64][64];
    float T[64][64];
    float gcs[64];
    float beta[64];
    float coef[64];
};
extern __shared__ float dyn_smem[];

__global__ void __launch_bounds__(128) prep_kernel(
    const float* __restrict__ gk, const float* __restrict__ gv, const float* __restrict__ gq,
    const float* __restrict__ gbeta, const float* __restrict__ ggcs,
    float* __restrict__ gu, float* __restrict__ gw, float* __restrict__ gattn) {
    PrepShm& S = *(PrepShm*)dyn_smem;
    int n = blockIdx.x, h = blockIdx.y;
    int tid = threadIdx.x;
    int base = h * T_LEN + n * 64;

    if (tid < 64) {
        S.gcs[tid]  = ggcs[base + tid];
        S.beta[tid] = gbeta[base + tid];
    }
    for (int idx = tid; idx < 64 * 128; idx += 128) {
        int i = idx >> 7, d = idx & 127;
        S.k[i][d] = gk[(size_t)(base + i) * DHEAD + d];
    }
    __syncthreads();
    for (int idx = tid; idx < 64 * 128; idx += 128) {
        int i = idx >> 7, d = idx & 127;
        S.x[i][d] = gv[(size_t)(base + i) * DHEAD + d] * S.beta[i];
    }
    for (int idx = tid; idx < 4096; idx += 128) {
        int i = idx >> 6, j = idx & 63;
        float val = 0.f;
        if (j < i) {
            float acc = 0.f;
            #pragma unroll 8
            for (int d = 0; d < 128; d++) {
                int dd = (d + tid) & 127;
                acc += S.k[i][dd] * S.k[j][dd];
            }
            val = acc * S.beta[i] * __expf(S.gcs[i] - S.gcs[j]);
        }
        S.A[i][j] = val;
    }
    __syncthreads();
    if (tid < 64) S.T[0][tid] = (tid == 0) ? 1.f : 0.f;
    __syncthreads();
    for (int i = 1; i < 64; i++) {
        if (tid < 64) {
            float acc = 0.f;
            for (int j = 0; j < i; j++) acc += S.A[i][j] * S.T[j][tid];
            S.T[i][tid] = ((tid == i) ? 1.f : 0.f) - acc;
        }
        __syncthreads();
    }
    if (tid < 64) S.coef[tid] = S.beta[tid] * __expf(S.gcs[tid]);
    __syncthreads();
    for (int idx = tid; idx < 64 * 128; idx += 128) {
        int i = idx >> 7, d = idx & 127;
        float au = 0.f, aw = 0.f;
        for (int j = 0; j <= i; j++) {
            float tij = S.T[i][j];
            au += tij * S.x[j][d];
            aw += tij * S.coef[j] * S.k[j][d];
        }
        gu[(size_t)(base + i) * DHEAD + d] = au;
        gw[(size_t)(base + i) * DHEAD + d] = aw;
    }
    __syncthreads();
    for (int idx = tid; idx < 64 * 128; idx += 128) {
        int i = idx >> 7, d = idx & 127;
        S.x[i][d] = gq[(size_t)(base + i) * DHEAD + d];
    }
    __syncthreads();
    float* attn_out = gattn + ((size_t)(h * 64 + n)) * 64 * 64;
    for (int idx = tid; idx < 4096; idx += 128) {
        int i = idx >> 6, j = idx & 63;
        float val = 0.f;
        if (j <= i) {
            float acc = 0.f;
            #pragma unroll 8
            for (int d = 0; d < 128; d++) {
                int dd = (d + tid) & 127;
                acc += S.x[i][dd] * S.k[j][dd];
            }
            val = acc * __expf(S.gcs[i] - S.gcs[j]);
        }
        attn_out[i * 64 + j] = val;
    }
}

// ---------------- sequential scan ----------------
#define DVS 16
struct ScanShm {
    float S[128][DVS];
    float w[64][132];
    float q[64][132];
    float k[64][132];
    float attn[64][68];
    float u[64][DVS];
    float vn[64][DVS];
    float gcs[64];
    float ex[64];
};

__global__ void __launch_bounds__(256) scan_kernel(
    const float* __restrict__ gq, const float* __restrict__ gk, const float* __restrict__ gw,
    const float* __restrict__ gu, const float* __restrict__ gattn, const float* __restrict__ ggcs,
    float* __restrict__ go) {
    ScanShm& S = *(ScanShm*)dyn_smem;
    int h = blockIdx.x;
    int dv0 = blockIdx.y * DVS;
    int tid = threadIdx.x;

    for (int idx = tid; idx < 128 * DVS; idx += 256) S.S[idx >> 4][idx & 15] = 0.f;

    for (int n = 0; n < NCHUNK; n++) {
        int base = h * T_LEN + n * 64;
        if (tid < 64) S.gcs[tid] = ggcs[base + tid];
        for (int idx = tid; idx < 64 * 128; idx += 256) {
            int i = idx >> 7, d = idx & 127;
            size_t gidx = (size_t)(base + i) * DHEAD + d;
            S.w[i][d] = gw[gidx];
            S.q[i][d] = gq[gidx];
            S.k[i][d] = gk[gidx];
        }
        const float* ap = gattn + ((size_t)(h * 64 + n)) * 64 * 64;
        for (int idx = tid; idx < 4096; idx += 256) S.attn[idx >> 6][idx & 63] = ap[idx];
        for (int idx = tid; idx < 64 * DVS; idx += 256) {
            int i = idx >> 4, dv = idx & 15;
            S.u[i][dv] = gu[(size_t)(base + i) * DHEAD + dv0 + dv];
        }
        __syncthreads();
        if (tid < 64) S.ex[tid] = __expf(S.gcs[63] - S.gcs[tid]);

        int i = tid >> 2, dvb = (tid & 3) * 4;
        {
            float4 uv = *(const float4*)&S.u[i][dvb];
            float a0 = uv.x, a1 = uv.y, a2 = uv.z, a3 = uv.w;
            for (int d = 0; d < 128; d++) {
                float wv = S.w[i][d];
                float4 sv = *(const float4*)&S.S[d][dvb];
                a0 -= wv * sv.x; a1 -= wv * sv.y; a2 -= wv * sv.z; a3 -= wv * sv.w;
            }
            float4 r; r.x = a0; r.y = a1; r.z = a2; r.w = a3;
            *(float4*)&S.vn[i][dvb] = r;
        }
        __syncthreads();
        {
            float a0 = 0, a1 = 0, a2 = 0, a3 = 0;
            for (int d = 0; d < 128; d++) {
                float qv = S.q[i][d];
                float4 sv = *(const float4*)&S.S[d][dvb];
                a0 += qv * sv.x; a1 += qv * sv.y; a2 += qv * sv.z; a3 += qv * sv.w;
            }
            float eg = __expf(S.gcs[i]);
            a0 *= eg; a1 *= eg; a2 *= eg; a3 *= eg;
            for (int j = 0; j <= i; j++) {
                float av = S.attn[i][j];
                float4 vv = *(const float4*)&S.vn[j][dvb];
                a0 += av * vv.x; a1 += av * vv.y; a2 += av * vv.z; a3 += av * vv.w;
            }
            float4 r; r.x = a0; r.y = a1; r.z = a2; r.w = a3;
            *(float4*)(go + (size_t)(base + i) * DHEAD + dv0 + dvb) = r;
        }
        __syncthreads();
        {
            float gle = __expf(S.gcs[63]);
            #pragma unroll
            for (int r = 0; r < 2; r++) {
                int qi = tid + 256 * r;
                int d = qi >> 2, db = (qi & 3) * 4;
                float4 sv = *(const float4*)&S.S[d][db];
                float a0 = sv.x * gle, a1 = sv.y * gle, a2 = sv.z * gle, a3 = sv.w * gle;
                for (int ii = 0; ii < 64; ii++) {
                    float kk = S.k[ii][d] * S.ex[ii];
                    float4 vv = *(const float4*)&S.vn[ii][db];
                    a0 += kk * vv.x; a1 += kk * vv.y; a2 += kk * vv.z; a3 += kk * vv.w;
                }
                float4 w4; w4.x = a0; w4.y = a1; w4.z = a2; w4.w = a3;
                *(float4*)&S.S[d][db] = w4;
            }
        }
        __syncthreads();
    }
}

// ---------------- gated RMSNorm * silu(z) -> bf16 hi/lo ----------------
__global__ void gated_out_kernel(const float* __restrict__ go, const float* __restrict__ qkvz,
                                 const float* __restrict__ onw,
                                 __nv_bfloat16* __restrict__ ochi, __nv_bfloat16* __restrict__ oclo) {
    int h = blockIdx.x, t = blockIdx.y, d = threadIdx.x;
    __shared__ float shm[32];
    float v = go[((size_t)h * T_LEN + t) * DHEAD + d];
    float ss = block_reduce_sum(v * v, shm, d, 128);
    float inv = rsqrtf(ss / 128.f + 1e-5f);
    float z = qkvz[(size_t)t * QKVZ_N + MIX_N + h * 128 + d];
    float res = v * inv * onw[d] * silu_f(z);
    __nv_bfloat16 hh, ll; split_hilo(res, hh, ll);
    size_t o = (size_t)t * DMODEL + h * 128 + d;
    ochi[o] = hh; oclo[o] = ll;
}

// ---------------- GLU -> bf16 hi/lo ----------------
__global__ void glu_kernel(const float* __restrict__ gate, const float* __restrict__ up,
                           __nv_bfloat16* __restrict__ ghi, __nv_bfloat16* __restrict__ glo) {
    int i = blockIdx.x * blockDim.x + threadIdx.x;
    float v = silu_f(gate[i]) * up[i];
    __nv_bfloat16 hh, ll; split_hilo(v, hh, ll);
    ghi[i] = hh; glo[i] = ll;
}

// ---------------- host launch ----------------
extern "C" void kernel_launch(void* const* d_in, const int* in_sizes, int n_in,
                              void* d_out, int out_size) {
    const float* x       = (const float*)d_in[0];
    const float* ln1_w   = (const float*)d_in[2];
    const float* qkvz_w  = (const float*)d_in[3];
    const float* ba_w    = (const float*)d_in[4];
    const float* conv_w  = (const float*)d_in[5];
    const float* A_log   = (const float*)d_in[6];
    const float* dt_bias = (const float*)d_in[7];
    const float* o_norm_w= (const float*)d_in[8];
    const float* out_w   = (const float*)d_in[9];
    const float* ln2_w   = (const float*)d_in[10];
    const float* gate_w  = (const float*)d_in[11];
    const float* up_w    = (const float*)d_in[12];
    const float* down_w  = (const float*)d_in[13];
    float* out = (float*)d_out;

    float *h, *qkvz, *ba, *qb, *kb, *vb, *beta, *gg, *gcs, *u, *w, *attn, *o, *x2, *up;
    cudaGetSymbolAddress((void**)&h,    g_h);
    cudaGetSymbolAddress((void**)&qkvz, g_qkvz);
    cudaGetSymbolAddress((void**)&ba,   g_ba);
    cudaGetSymbolAddress((void**)&qb,   g_qb);
    cudaGetSymbolAddress((void**)&kb,   g_kb);
    cudaGetSymbolAddress((void**)&vb,   g_vb);
    cudaGetSymbolAddress((void**)&beta, g_beta);
    cudaGetSymbolAddress((void**)&gg,   g_g);
    cudaGetSymbolAddress((void**)&gcs,  g_gcs);
    cudaGetSymbolAddress((void**)&u,    g_u);
    cudaGetSymbolAddress((void**)&w,    g_wb);
    cudaGetSymbolAddress((void**)&attn, g_attn);
    cudaGetSymbolAddress((void**)&o,    g_o);
    cudaGetSymbolAddress((void**)&x2,   g_x2);
    cudaGetSymbolAddress((void**)&up,   g_up);

    __nv_bfloat16 *hhi, *hlo, *ochi, *oclo, *guhi, *gulo;
    __nv_bfloat16 *w1hi, *w1lo, *wohi, *wolo, *wghi, *wglo, *wuhi, *wulo, *wdhi, *wdlo;
    cudaGetSymbolAddress((void**)&hhi,  b_h_hi);
    cudaGetSymbolAddress((void**)&hlo,  b_h_lo);
    cudaGetSymbolAddress((void**)&ochi, b_oc_hi);
    cudaGetSymbolAddress((void**)&oclo, b_oc_lo);
    cudaGetSymbolAddress((void**)&guhi, b_gu_hi);
    cudaGetSymbolAddress((void**)&gulo, b_gu_lo);
    cudaGetSymbolAddress((void**)&w1hi, b_w1_hi);
    cudaGetSymbolAddress((void**)&w1lo, b_w1_lo);
    cudaGetSymbolAddress((void**)&wohi, b_wo_hi);
    cudaGetSymbolAddress((void**)&wolo, b_wo_lo);
    cudaGetSymbolAddress((void**)&wghi, b_wg_hi);
    cudaGetSymbolAddress((void**)&wglo, b_wg_lo);
    cudaGetSymbolAddress((void**)&wuhi, b_wu_hi);
    cudaGetSymbolAddress((void**)&wulo, b_wu_lo);
    cudaGetSymbolAddress((void**)&wdhi, b_wd_hi);
    cudaGetSymbolAddress((void**)&wdlo, b_wd_lo);

    cudaFuncSetAttribute(prep_kernel, cudaFuncAttributeMaxDynamicSharedMemorySize, (int)sizeof(PrepShm));
    cudaFuncSetAttribute(scan_kernel, cudaFuncAttributeMaxDynamicSharedMemorySize, (int)sizeof(ScanShm));
    const int GSMEM = 4 * GSTAGE;
    cudaFuncSetAttribute(gemm_tc, cudaFuncAttributeMaxDynamicSharedMemorySize, GSMEM);

    // weight conversions
    cvt_hilo<<<(QKVZ_N * DMODEL) / 1024, 256>>>(qkvz_w, w1hi, w1lo, QKVZ_N * DMODEL);
    cvt_hilo<<<(DMODEL * DMODEL) / 1024, 256>>>(out_w,  wohi, wolo, DMODEL * DMODEL);
    cvt_hilo<<<(MDIM * DMODEL) / 1024, 256>>>(gate_w, wghi, wglo, MDIM * DMODEL);
    cvt_hilo<<<(MDIM * DMODEL) / 1024, 256>>>(up_w,   wuhi, wulo, MDIM * DMODEL);
    cvt_hilo<<<(DMODEL * MDIM) / 1024, 256>>>(down_w, wdhi, wdlo, DMODEL * MDIM);

    // 1) h = rms(x, ln1) (+ hi/lo)
    rmsnorm_kernel<<<T_LEN, 256>>>(x, ln1_w, h, hhi, hlo);
    // 2) qkvz = h @ qkvz_w^T ; ba = h @ ba_w^T
    gemm_tc<<<dim3(QKVZ_N / 128, T_LEN / 128), 256, GSMEM>>>(hhi, hlo, w1hi, w1lo, (const float*)0, qkvz, T_LEN, QKVZ_N, DMODEL);
    gemm_n32<<<T_LEN / 32, 256>>>(h, ba_w, ba, DMODEL);
    // 3) conv + silu + l2norm
    conv_kernel<<<dim3(48, T_LEN), 128>>>(qkvz, conv_w, qb, kb, vb);
    // 4) beta, g, gcs
    betag_kernel<<<(NHEAD * T_LEN + 255) / 256, 256>>>(ba, A_log, dt_bias, beta, gg);
    gcs_kernel<<<NHEAD * NCHUNK, 64>>>(gg, gcs);
    // 5) chunk prep
    prep_kernel<<<dim3(NCHUNK, NHEAD), 128, sizeof(PrepShm)>>>(kb, vb, qb, beta, gcs, u, w, attn);
    // 6) scan
    scan_kernel<<<dim3(NHEAD, DHEAD / DVS), 256, sizeof(ScanShm)>>>(qb, kb, w, u, attn, gcs, o);
    // 7) gated norm * silu(z) -> oc hi/lo
    gated_out_kernel<<<dim3(NHEAD, T_LEN), 128>>>(o, qkvz, o_norm_w, ochi, oclo);
    // 8) x2 = x + oc @ out_w^T
    gemm_tc<<<dim3(DMODEL / 128, T_LEN / 128), 256, GSMEM>>>(ochi, oclo, wohi, wolo, x, x2, T_LEN, DMODEL, DMODEL);
    // 9) h2 = rms(x2, ln2)
    rmsnorm_kernel<<<T_LEN, 256>>>(x2, ln2_w, h, hhi, hlo);
    // 10) gate, up GEMMs
    gemm_tc<<<dim3(MDIM / 128, T_LEN / 128), 256, GSMEM>>>(hhi, hlo, wghi, wglo, (const float*)0, qkvz, T_LEN, MDIM, DMODEL);
    gemm_tc<<<dim3(MDIM / 128, T_LEN / 128), 256, GSMEM>>>(hhi, hlo, wuhi, wulo, (const float*)0, up, T_LEN, MDIM, DMODEL);
    // 11) gu = silu(gate) * up -> hi/lo
    glu_kernel<<<(T_LEN * MDIM) / 256, 256>>>(qkvz, up, guhi, gulo);
    // 12) out = x2 + gu @ down_w^T
    gemm_tc<<<dim3(DMODEL / 128, T_LEN / 128), 256, GSMEM>>>(guhi, gulo, wdhi, wdlo, x2, out, T_LEN, DMODEL, MDIM);
}

// round 7
// speedup vs baseline: 2.3942x; 1.1636x over previous
#include <cuda_runtime.h>
#include <cuda_bf16.h>
#include <math.h>
#include <stdint.h>

// ---------------- Problem constants (B=1) ----------------
#define T_LEN   4096
#define DMODEL  2048
#define NHEAD   16
#define DHEAD   128
#define NCHUNK  64
#define CLEN    64
#define QKVZ_N  8192   // 2*kd + 2*vd
#define MIX_N   6144   // q+k+v channels
#define MDIM    8192

// ---------------- fp32 scratch ----------------
__device__ float g_h   [T_LEN * DMODEL];
__device__ float g_qkvz[T_LEN * QKVZ_N];
__device__ float g_ba  [T_LEN * 32];
__device__ float g_qb  [NHEAD * T_LEN * DHEAD];
__device__ float g_kb  [NHEAD * T_LEN * DHEAD];
__device__ float g_vb  [NHEAD * T_LEN * DHEAD];
__device__ float g_beta[NHEAD * T_LEN];
__device__ float g_g   [NHEAD * T_LEN];
__device__ float g_gcs [NHEAD * T_LEN];
__device__ float g_u   [NHEAD * T_LEN * DHEAD];
__device__ float g_wb  [NHEAD * T_LEN * DHEAD];
__device__ float g_attn[NHEAD * NCHUNK * CLEN * CLEN];
__device__ float g_o   [NHEAD * T_LEN * DHEAD];
__device__ float g_x2  [T_LEN * DMODEL];
__device__ float g_up  [T_LEN * MDIM];

// ---------------- bf16 hi/lo scratch ----------------
__device__ __nv_bfloat16 b_h_hi [T_LEN * DMODEL];
__device__ __nv_bfloat16 b_h_lo [T_LEN * DMODEL];
__device__ __nv_bfloat16 b_oc_hi[T_LEN * DMODEL];
__device__ __nv_bfloat16 b_oc_lo[T_LEN * DMODEL];
__device__ __nv_bfloat16 b_gu_hi[T_LEN * MDIM];
__device__ __nv_bfloat16 b_gu_lo[T_LEN * MDIM];
__device__ __nv_bfloat16 b_w1_hi[QKVZ_N * DMODEL];
__device__ __nv_bfloat16 b_w1_lo[QKVZ_N * DMODEL];
__device__ __nv_bfloat16 b_wo_hi[DMODEL * DMODEL];
__device__ __nv_bfloat16 b_wo_lo[DMODEL * DMODEL];
__device__ __nv_bfloat16 b_wg_hi[MDIM * DMODEL];
__device__ __nv_bfloat16 b_wg_lo[MDIM * DMODEL];
__device__ __nv_bfloat16 b_wu_hi[MDIM * DMODEL];
__device__ __nv_bfloat16 b_wu_lo[MDIM * DMODEL];
__device__ __nv_bfloat16 b_wd_hi[DMODEL * MDIM];
__device__ __nv_bfloat16 b_wd_lo[DMODEL * MDIM];

// ---------------- PTX helpers (sm_103-safe) ----------------
__device__ __forceinline__ uint32_t smem_u32(const void* p) {
    uint32_t a;
    asm("{ .reg .u64 t; cvta.to.shared.u64 t, %1; cvt.u32.u64 %0, t; }" : "=r"(a) : "l"(p));
    return a;
}
#define CP_ASYNC16(d,s) asm volatile("cp.async.cg.shared.global [%0], [%1], 16;" :: "r"(d), "l"(s))
#define CP_COMMIT()     asm volatile("cp.async.commit_group;" ::: "memory")
#define CP_WAIT2()      asm volatile("cp.async.wait_group 2;" ::: "memory")
#define CP_WAIT1()      asm volatile("cp.async.wait_group 1;" ::: "memory")
#define CP_WAIT0()      asm volatile("cp.async.wait_group 0;" ::: "memory")

__device__ __forceinline__ void ldsm4(uint32_t addr, uint32_t* o) {
    uint32_t r0, r1, r2, r3;
    asm volatile("ldmatrix.sync.aligned.m8n8.x4.shared.b16 {%0,%1,%2,%3}, [%4];"
        : "=r"(r0), "=r"(r1), "=r"(r2), "=r"(r3) : "r"(addr));
    o[0] = r0; o[1] = r1; o[2] = r2; o[3] = r3;
}

__device__ __forceinline__ void mma16816(float* d, uint32_t a0, uint32_t a1, uint32_t a2,
                                         uint32_t a3, uint32_t b0, uint32_t b1) {
    float t0 = d[0], t1 = d[1], t2 = d[2], t3 = d[3];
    asm volatile("mma.sync.aligned.m16n8k16.row.col.f32.bf16.bf16.f32 "
        "{%0,%1,%2,%3},{%4,%5,%6,%7},{%8,%9},{%0,%1,%2,%3};"
        : "+f"(t0), "+f"(t1), "+f"(t2), "+f"(t3)
        : "r"(a0), "r"(a1), "r"(a2), "r"(a3), "r"(b0), "r"(b1));
    d[0] = t0; d[1] = t1; d[2] = t2; d[3] = t3;
}

// ---------------- helpers ----------------
__device__ __forceinline__ float block_reduce_sum(float v, float* shm, int tid, int nthreads) {
    #pragma unroll
    for (int o = 16; o; o >>= 1) v += __shfl_down_sync(0xffffffffu, v, o);
    __syncthreads();
    if ((tid & 31) == 0) shm[tid >> 5] = v;
    __syncthreads();
    int nw = nthreads >> 5;
    float s = (tid < nw) ? shm[tid] : 0.f;
    if (tid < 32) {
        #pragma unroll
        for (int o = 16; o; o >>= 1) s += __shfl_down_sync(0xffffffffu, s, o);
        if (tid == 0) shm[0] = s;
    }
    __syncthreads();
    return shm[0];
}
__device__ __forceinline__ float silu_f(float x) { return x / (1.f + __expf(-x)); }
__device__ __forceinline__ void split_hilo(float x, __nv_bfloat16& h, __nv_bfloat16& l) {
    h = __float2bfloat16(x);
    l = __float2bfloat16(x - __bfloat162float(h));
}

// ---------------- weight fp32 -> bf16 hi/lo ----------------
__global__ void cvt_hilo(const float* __restrict__ x, __nv_bfloat16* __restrict__ hi,
                         __nv_bfloat16* __restrict__ lo, int n) {
    int i = (blockIdx.x * blockDim.x + threadIdx.x) * 4;
    if (i >= n) return;
    float4 v = *(const float4*)(x + i);
    __nv_bfloat16 h0, h1, h2, h3, l0, l1, l2, l3;
    split_hilo(v.x, h0, l0); split_hilo(v.y, h1, l1);
    split_hilo(v.z, h2, l2); split_hilo(v.w, h3, l3);
    __nv_bfloat162* hp = (__nv_bfloat162*)(hi + i);
    __nv_bfloat162* lp = (__nv_bfloat162*)(lo + i);
    hp[0] = __nv_bfloat162(h0, h1); hp[1] = __nv_bfloat162(h2, h3);
    lp[0] = __nv_bfloat162(l0, l1); lp[1] = __nv_bfloat162(l2, l3);
}

// ---------------- RMSNorm + hi/lo ----------------
__global__ void rmsnorm_kernel(const float* __restrict__ x, const float* __restrict__ w,
                               float* __restrict__ y, __nv_bfloat16* __restrict__ yhi,
                               __nv_bfloat16* __restrict__ ylo) {
    int t = blockIdx.x, tid = threadIdx.x;
    __shared__ float shm[32];
    const float* xr = x + (size_t)t * DMODEL;
    float ss = 0.f;
    for (int d = tid; d < DMODEL; d += 256) { float v = xr[d]; ss += v * v; }
    ss = block_reduce_sum(ss, shm, tid, 256);
    float inv = rsqrtf(ss / (float)DMODEL + 1e-5f);
    for (int d = tid; d < DMODEL; d += 256) {
        float v = xr[d] * inv * w[d];
        y[(size_t)t * DMODEL + d] = v;
        __nv_bfloat16 h, l; split_hilo(v, h, l);
        yhi[(size_t)t * DMODEL + d] = h;
        ylo[(size_t)t * DMODEL + d] = l;
    }
}

// ---------------- HMMA GEMM, fused 3-term split ----------------
// C[M,N] = A@B^T (+R). Per K-stage (BK=32) load Ahi|Alo|Bhi|Blo (32KB) once,
// run 3 MMA groups: hi*hi, lo*hi, hi*lo, all accumulated in fp32 registers.
// 128x128 tile, 8 warps (4x2), warp tile 32x64, 3-buffer cp.async pipeline.
#define GSTAGE 32768   // Ahi 8K | Alo 8K | Bhi 8K | Blo 8K
__global__ void __launch_bounds__(256, 2) gemm_tc(
    const __nv_bfloat16* __restrict__ Ahi, const __nv_bfloat16* __restrict__ Alo,
    const __nv_bfloat16* __restrict__ Bhi, const __nv_bfloat16* __restrict__ Blo,
    const float* __restrict__ R, float* __restrict__ C, int M, int N, int K) {
    extern __shared__ char smem_raw[];
    uint32_t sbase = smem_u32(smem_raw);
    int tid = threadIdx.x, lane = tid & 31, warp = tid >> 5;
    int wm = warp >> 1, wn = warp & 1;
    int m0 = blockIdx.y * 128, n0 = blockIdx.x * 128;
    const int TS = K >> 5;

    float acc[2][8][4];
    #pragma unroll
    for (int a = 0; a < 2; a++)
        #pragma unroll
        for (int b = 0; b < 8; b++)
            #pragma unroll
            for (int c = 0; c < 4; c++) acc[a][b][c] = 0.f;

    // per-lane ldmatrix offsets (region-relative), both k-steps
    uint32_t aoff[2][2], boff[4][2];
    {
        int mat = lane >> 3, r = lane & 7;
        #pragma unroll
        for (int mt = 0; mt < 2; mt++) {
            int row = wm * 32 + mt * 16 + ((mat & 1) << 3) + r;
            #pragma unroll
            for (int ks = 0; ks < 2; ks++) {
                int ch = (ks << 1) + (mat >> 1);
                aoff[mt][ks] = row * 64 + ((ch ^ ((row >> 1) & 3)) << 4);
            }
        }
        #pragma unroll
        for (int j = 0; j < 4; j++) {
            int row = wn * 64 + j * 16 + ((mat >> 1) << 3) + r;
            #pragma unroll
            for (int ks = 0; ks < 2; ks++) {
                int ch = (ks << 1) + (mat & 1);
                boff[j][ks] = row * 64 + ((ch ^ ((row >> 1) & 3)) << 4);
            }
        }
    }

    // loader: per thread 2 (row, chunk) pairs, replicated across the 4 regions
    int lrow[2], lc[2]; uint32_t lso[2];
    #pragma unroll
    for (int i = 0; i < 2; i++) {
        int id = (tid << 1) | i;
        lrow[i] = id >> 2; lc[i] = id & 3;
        lso[i] = lrow[i] * 64 + ((lc[i] ^ ((lrow[i] >> 1) & 3)) << 4);
    }

    auto load_stage = [&](int st) {
        int buf = st % 3;
        int k0 = st << 5;
        uint32_t bb = sbase + buf * GSTAGE;
        #pragma unroll
        for (int i = 0; i < 2; i++) {
            size_t aidx = (size_t)(m0 + lrow[i]) * K + k0 + lc[i] * 8;
            size_t bidx = (size_t)(n0 + lrow[i]) * K + k0 + lc[i] * 8;
            CP_ASYNC16(bb + lso[i],         Ahi + aidx);
            CP_ASYNC16(bb + 8192  + lso[i], Alo + aidx);
            CP_ASYNC16(bb + 16384 + lso[i], Bhi + bidx);
            CP_ASYNC16(bb + 24576 + lso[i], Blo + bidx);
        }
        CP_COMMIT();
    };

    load_stage(0); load_stage(1); load_stage(2);

    for (int st = 0; st < TS; st++) {
        int rem = TS - 1 - st;
        if (rem >= 2) { CP_WAIT2(); } else if (rem == 1) { CP_WAIT1(); } else { CP_WAIT0(); }
        __syncthreads();

        uint32_t stb = sbase + (st % 3) * GSTAGE;
        #pragma unroll
        for (int ks = 0; ks < 2; ks++) {
            uint32_t af[2][4], bf[4][4];
            // term0: Ahi * Bhi
            ldsm4(stb + aoff[0][ks], af[0]);
            ldsm4(stb + aoff[1][ks], af[1]);
            #pragma unroll
            for (int j = 0; j < 4; j++) ldsm4(stb + 16384 + boff[j][ks], bf[j]);
            #pragma unroll
            for (int mt = 0; mt < 2; mt++)
                #pragma unroll
                for (int j = 0; j < 4; j++) {
                    mma16816(&acc[mt][2 * j][0],     af[mt][0], af[mt][1], af[mt][2], af[mt][3], bf[j][0], bf[j][1]);
                    mma16816(&acc[mt][2 * j + 1][0], af[mt][0], af[mt][1], af[mt][2], af[mt][3], bf[j][2], bf[j][3]);
                }
            // term1: Alo * Bhi (reuse B frags)
            ldsm4(stb + 8192 + aoff[0][ks], af[0]);
            ldsm4(stb + 8192 + aoff[1][ks], af[1]);
            #pragma unroll
            for (int mt = 0; mt < 2; mt++)
                #pragma unroll
                for (int j = 0; j < 4; j++) {
                    mma16816(&acc[mt][2 * j][0],     af[mt][0], af[mt][1], af[mt][2], af[mt][3], bf[j][0], bf[j][1]);
                    mma16816(&acc[mt][2 * j + 1][0], af[mt][0], af[mt][1], af[mt][2], af[mt][3], bf[j][2], bf[j][3]);
                }
            // term2: Ahi * Blo
            ldsm4(stb + aoff[0][ks], af[0]);
            ldsm4(stb + aoff[1][ks], af[1]);
            #pragma unroll
            for (int j = 0; j < 4; j++) ldsm4(stb + 24576 + boff[j][ks], bf[j]);
            #pragma unroll
            for (int mt = 0; mt < 2; mt++)
                #pragma unroll
                for (int j = 0; j < 4; j++) {
                    mma16816(&acc[mt][2 * j][0],     af[mt][0], af[mt][1], af[mt][2], af[mt][3], bf[j][0], bf[j][1]);
                    mma16816(&acc[mt][2 * j + 1][0], af[mt][0], af[mt][1], af[mt][2], af[mt][3], bf[j][2], bf[j][3]);
                }
        }
        __syncthreads();
        if (st + 3 < TS) load_stage(st + 3);
    }

    // epilogue
    #pragma unroll
    for (int mt = 0; mt < 2; mt++) {
        #pragma unroll
        for (int nt = 0; nt < 8; nt++) {
            int rr = m0 + wm * 32 + mt * 16 + (lane >> 2);
            int cc = n0 + wn * 64 + nt * 8 + ((lane & 3) << 1);
            float2 v0, v1;
            v0.x = acc[mt][nt][0]; v0.y = acc[mt][nt][1];
            v1.x = acc[mt][nt][2]; v1.y = acc[mt][nt][3];
            if (R != 0) {
                const float2 r0 = *(const float2*)(R + (size_t)rr * N + cc);
                const float2 r1 = *(const float2*)(R + (size_t)(rr + 8) * N + cc);
                v0.x += r0.x; v0.y += r0.y; v1.x += r1.x; v1.y += r1.y;
            }
            *(float2*)(C + (size_t)rr * N + cc) = v0;
            *(float2*)(C + (size_t)(rr + 8) * N + cc) = v1;
        }
    }
}

// ---------------- small-N GEMM for ba ----------------
__global__ void gemm_n32(const float* __restrict__ A, const float* __restrict__ B,
                         float* __restrict__ C, int K) {
    __shared__ float hs[32][65];
    __shared__ float ws[32][65];
    int m0 = blockIdx.x * 32;
    int tid = threadIdx.x;
    int c = tid & 31, r0 = tid >> 5;
    float acc[4] = {0, 0, 0, 0};
    for (int k0 = 0; k0 < K; k0 += 64) {
        __syncthreads();
        for (int idx = tid; idx < 2048; idx += 256) {
            int r = idx >> 6, kk = idx & 63;
            hs[r][kk] = A[(size_t)(m0 + r) * K + k0 + kk];
            ws[r][kk] = B[(size_t)r * K + k0 + kk];
        }
        __syncthreads();
        for (int kk = 0; kk < 64; kk++) {
            float wv = ws[c][kk];
            #pragma unroll
            for (int s = 0; s < 4; s++) acc[s] += hs[r0 + 8 * s][kk] * wv;
        }
    }
    #pragma unroll
    for (int s = 0; s < 4; s++) C[(size_t)(m0 + r0 + 8 * s) * 32 + c] = acc[s];
}

// ---------------- causal conv + silu + l2norm + head split ----------------
__global__ void conv_kernel(const float* __restrict__ qkvz, const float* __restrict__ conv_w,
                            float* __restrict__ qo, float* __restrict__ ko, float* __restrict__ vo) {
    int t = blockIdx.y;
    int wh = blockIdx.x;
    int which = wh >> 4, head = wh & 15;
    int d = threadIdx.x;
    int c = which * 2048 + head * 128 + d;
    float acc = 0.f;
    #pragma unroll
    for (int j = 0; j < 4; j++) {
        int tt = t - 3 + j;
        if (tt >= 0) acc += qkvz[(size_t)tt * QKVZ_N + c] * conv_w[c * 4 + j];
    }
    float s = silu_f(acc);
    size_t oidx = ((size_t)head * T_LEN + t) * DHEAD + d;
    if (which == 2) { vo[oidx] = s; return; }
    __shared__ float shm[32];
    float ss = block_reduce_sum(s * s, shm, d, 128);
    float val = s * rsqrtf(ss + 1e-6f);
    if (which == 0) val *= 0.08838834764831845f;
    (which == 0 ? qo : ko)[oidx] = val;
}

// ---------------- beta / g ----------------
__global__ void betag_kernel(const float* __restrict__ ba, const float* __restrict__ A_log,
                             const float* __restrict__ dt_bias,
                             float* __restrict__ beta, float* __restrict__ g) {
    int idx = blockIdx.x * blockDim.x + threadIdx.x;
    if (idx >= NHEAD * T_LEN) return;
    int t = idx >> 4, h = idx & 15;
    float b = ba[t * 32 + h];
    float a = ba[t * 32 + 16 + h];
    beta[h * T_LEN + t] = 1.f / (1.f + expf(-b));
    float xx = a + dt_bias[h];
    float sp = (xx > 20.f) ? xx : log1pf(expf(xx));
    g[h * T_LEN + t] = -expf(A_log[h]) * sp;
}

// ---------------- within-chunk cumsum of g ----------------
__global__ void gcs_kernel(const float* __restrict__ g, float* __restrict__ gcs) {
    int h = blockIdx.x >> 6, n = blockIdx.x & 63;
    __shared__ float s[64];
    int i = threadIdx.x;
    int base = h * T_LEN + n * 64;
    s[i] = g[base + i];
    __syncthreads();
    for (int off = 1; off < 64; off <<= 1) {
        float v = (i >= off) ? s[i - off] : 0.f;
        __syncthreads();
        s[i] += v;
        __syncthreads();
    }
    gcs[base + i] = s[i];
}

// ---------------- per-chunk prep: A, T=(I+A)^-1, u, w, attn ----------------
struct PrepShm {
    float k[64][128];
    float x[64][128];
    float A[64][64];
    float T[64][64];
    float gcs[64];
    float beta[64];
    float coef[64];
};
extern __shared__ float dyn_smem[];

__global__ void __launch_bounds__(128) prep_kernel(
    const float* __restrict__ gk, const float* __restrict__ gv, const float* __restrict__ gq,
    const float* __restrict__ gbeta, const float* __restrict__ ggcs,
    float* __restrict__ gu, float* __restrict__ gw, float* __restrict__ gattn) {
    PrepShm& S = *(PrepShm*)dyn_smem;
    int n = blockIdx.x, h = blockIdx.y;
    int tid = threadIdx.x;
    int base = h * T_LEN + n * 64;

    if (tid < 64) {
        S.gcs[tid]  = ggcs[base + tid];
        S.beta[tid] = gbeta[base + tid];
    }
    for (int idx = tid; idx < 64 * 128; idx += 128) {
        int i = idx >> 7, d = idx & 127;
        S.k[i][d] = gk[(size_t)(base + i) * DHEAD + d];
    }
    __syncthreads();
    for (int idx = tid; idx < 64 * 128; idx += 128) {
        int i = idx >> 7, d = idx & 127;
        S.x[i][d] = gv[(size_t)(base + i) * DHEAD + d] * S.beta[i];
    }
    for (int idx = tid; idx < 4096; idx += 128) {
        int i = idx >> 6, j = idx & 63;
        float val = 0.f;
        if (j < i) {
            float acc = 0.f;
            #pragma unroll 8
            for (int d = 0; d < 128; d++) {
                int dd = (d + tid) & 127;
                acc += S.k[i][dd] * S.k[j][dd];
            }
            val = acc * S.beta[i] * __expf(S.gcs[i] - S.gcs[j]);
        }
        S.A[i][j] = val;
    }
    __syncthreads();
    if (tid < 64) S.T[0][tid] = (tid == 0) ? 1.f : 0.f;
    __syncthreads();
    for (int i = 1; i < 64; i++) {
        if (tid < 64) {
            float acc = 0.f;
            for (int j = 0; j < i; j++) acc += S.A[i][j] * S.T[j][tid];
            S.T[i][tid] = ((tid == i) ? 1.f : 0.f) - acc;
        }
        __syncthreads();
    }
    if (tid < 64) S.coef[tid] = S.beta[tid] * __expf(S.gcs[tid]);
    __syncthreads();
    for (int idx = tid; idx < 64 * 128; idx += 128) {
        int i = idx >> 7, d = idx & 127;
        float au = 0.f, aw = 0.f;
        for (int j = 0; j <= i; j++) {
            float tij = S.T[i][j];
            au += tij * S.x[j][d];
            aw += tij * S.coef[j] * S.k[j][d];
        }
        gu[(size_t)(base + i) * DHEAD + d] = au;
        gw[(size_t)(base + i) * DHEAD + d] = aw;
    }
    __syncthreads();
    for (int idx = tid; idx < 64 * 128; idx += 128) {
        int i = idx >> 7, d = idx & 127;
        S.x[i][d] = gq[(size_t)(base + i) * DHEAD + d];
    }
    __syncthreads();
    float* attn_out = gattn + ((size_t)(h * 64 + n)) * 64 * 64;
    for (int idx = tid; idx < 4096; idx += 128) {
        int i = idx >> 6, j = idx & 63;
        float val = 0.f;
        if (j <= i) {
            float acc = 0.f;
            #pragma unroll 8
            for (int d = 0; d < 128; d++) {
                int dd = (d + tid) & 127;
                acc += S.x[i][dd] * S.k[j][dd];
            }
            val = acc * __expf(S.gcs[i] - S.gcs[j]);
        }
        attn_out[i * 64 + j] = val;
    }
}

// ---------------- sequential scan ----------------
#define DVS 16
struct ScanShm {
    float S[128][DVS];
    float w[64][132];
    float q[64][132];
    float k[64][132];
    float attn[64][68];
    float u[64][DVS];
    float vn[64][DVS];
    float gcs[64];
    float ex[64];
};

__global__ void __launch_bounds__(256) scan_kernel(
    const float* __restrict__ gq, const float* __restrict__ gk, const float* __restrict__ gw,
    const float* __restrict__ gu, const float* __restrict__ gattn, const float* __restrict__ ggcs,
    float* __restrict__ go) {
    ScanShm& S = *(ScanShm*)dyn_smem;
    int h = blockIdx.x;
    int dv0 = blockIdx.y * DVS;
    int tid = threadIdx.x;

    for (int idx = tid; idx < 128 * DVS; idx += 256) S.S[idx >> 4][idx & 15] = 0.f;

    for (int n = 0; n < NCHUNK; n++) {
        int base = h * T_LEN + n * 64;
        if (tid < 64) S.gcs[tid] = ggcs[base + tid];
        for (int idx = tid; idx < 64 * 128; idx += 256) {
            int i = idx >> 7, d = idx & 127;
            size_t gidx = (size_t)(base + i) * DHEAD + d;
            S.w[i][d] = gw[gidx];
            S.q[i][d] = gq[gidx];
            S.k[i][d] = gk[gidx];
        }
        const float* ap = gattn + ((size_t)(h * 64 + n)) * 64 * 64;
        for (int idx = tid; idx < 4096; idx += 256) S.attn[idx >> 6][idx & 63] = ap[idx];
        for (int idx = tid; idx < 64 * DVS; idx += 256) {
            int i = idx >> 4, dv = idx & 15;
            S.u[i][dv] = gu[(size_t)(base + i) * DHEAD + dv0 + dv];
        }
        __syncthreads();
        if (tid < 64) S.ex[tid] = __expf(S.gcs[63] - S.gcs[tid]);

        int i = tid >> 2, dvb = (tid & 3) * 4;
        {
            float4 uv = *(const float4*)&S.u[i][dvb];
            float a0 = uv.x, a1 = uv.y, a2 = uv.z, a3 = uv.w;
            for (int d = 0; d < 128; d++) {
                float wv = S.w[i][d];
                float4 sv = *(const float4*)&S.S[d][dvb];
                a0 -= wv * sv.x; a1 -= wv * sv.y; a2 -= wv * sv.z; a3 -= wv * sv.w;
            }
            float4 r; r.x = a0; r.y = a1; r.z = a2; r.w = a3;
            *(float4*)&S.vn[i][dvb] = r;
        }
        __syncthreads();
        {
            float a0 = 0, a1 = 0, a2 = 0, a3 = 0;
            for (int d = 0; d < 128; d++) {
                float qv = S.q[i][d];
                float4 sv = *(const float4*)&S.S[d][dvb];
                a0 += qv * sv.x; a1 += qv * sv.y; a2 += qv * sv.z; a3 += qv * sv.w;
            }
            float eg = __expf(S.gcs[i]);
            a0 *= eg; a1 *= eg; a2 *= eg; a3 *= eg;
            for (int j = 0; j <= i; j++) {
                float av = S.attn[i][j];
                float4 vv = *(const float4*)&S.vn[j][dvb];
                a0 += av * vv.x; a1 += av * vv.y; a2 += av * vv.z; a3 += av * vv.w;
            }
            float4 r; r.x = a0; r.y = a1; r.z = a2; r.w = a3;
            *(float4*)(go + (size_t)(base + i) * DHEAD + dv0 + dvb) = r;
        }
        __syncthreads();
        {
            float gle = __expf(S.gcs[63]);
            #pragma unroll
            for (int r = 0; r < 2; r++) {
                int qi = tid + 256 * r;
                int d = qi >> 2, db = (qi & 3) * 4;
                float4 sv = *(const float4*)&S.S[d][db];
                float a0 = sv.x * gle, a1 = sv.y * gle, a2 = sv.z * gle, a3 = sv.w * gle;
                for (int ii = 0; ii < 64; ii++) {
                    float kk = S.k[ii][d] * S.ex[ii];
                    float4 vv = *(const float4*)&S.vn[ii][db];
                    a0 += kk * vv.x; a1 += kk * vv.y; a2 += kk * vv.z; a3 += kk * vv.w;
                }
                float4 w4; w4.x = a0; w4.y = a1; w4.z = a2; w4.w = a3;
                *(float4*)&S.S[d][db] = w4;
            }
        }
        __syncthreads();
    }
}

// ---------------- gated RMSNorm * silu(z) -> bf16 hi/lo ----------------
__global__ void gated_out_kernel(const float* __restrict__ go, const float* __restrict__ qkvz,
                                 const float* __restrict__ onw,
                                 __nv_bfloat16* __restrict__ ochi, __nv_bfloat16* __restrict__ oclo) {
    int h = blockIdx.x, t = blockIdx.y, d = threadIdx.x;
    __shared__ float shm[32];
    float v = go[((size_t)h * T_LEN + t) * DHEAD + d];
    float ss = block_reduce_sum(v * v, shm, d, 128);
    float inv = rsqrtf(ss / 128.f + 1e-5f);
    float z = qkvz[(size_t)t * QKVZ_N + MIX_N + h * 128 + d];
    float res = v * inv * onw[d] * silu_f(z);
    __nv_bfloat16 hh, ll; split_hilo(res, hh, ll);
    size_t o = (size_t)t * DMODEL + h * 128 + d;
    ochi[o] = hh; oclo[o] = ll;
}

// ---------------- GLU -> bf16 hi/lo ----------------
__global__ void glu_kernel(const float* __restrict__ gate, const float* __restrict__ up,
                           __nv_bfloat16* __restrict__ ghi, __nv_bfloat16* __restrict__ glo) {
    int i = blockIdx.x * blockDim.x + threadIdx.x;
    float v = silu_f(gate[i]) * up[i];
    __nv_bfloat16 hh, ll; split_hilo(v, hh, ll);
    ghi[i] = hh; glo[i] = ll;
}

// ---------------- host launch ----------------
extern "C" void kernel_launch(void* const* d_in, const int* in_sizes, int n_in,
                              void* d_out, int out_size) {
    const float* x       = (const float*)d_in[0];
    const float* ln1_w   = (const float*)d_in[2];
    const float* qkvz_w  = (const float*)d_in[3];
    const float* ba_w    = (const float*)d_in[4];
    const float* conv_w  = (const float*)d_in[5];
    const float* A_log   = (const float*)d_in[6];
    const float* dt_bias = (const float*)d_in[7];
    const float* o_norm_w= (const float*)d_in[8];
    const float* out_w   = (const float*)d_in[9];
    const float* ln2_w   = (const float*)d_in[10];
    const float* gate_w  = (const float*)d_in[11];
    const float* up_w    = (const float*)d_in[12];
    const float* down_w  = (const float*)d_in[13];
    float* out = (float*)d_out;

    float *h, *qkvz, *ba, *qb, *kb, *vb, *beta, *gg, *gcs, *u, *w, *attn, *o, *x2, *up;
    cudaGetSymbolAddress((void**)&h,    g_h);
    cudaGetSymbolAddress((void**)&qkvz, g_qkvz);
    cudaGetSymbolAddress((void**)&ba,   g_ba);
    cudaGetSymbolAddress((void**)&qb,   g_qb);
    cudaGetSymbolAddress((void**)&kb,   g_kb);
    cudaGetSymbolAddress((void**)&vb,   g_vb);
    cudaGetSymbolAddress((void**)&beta, g_beta);
    cudaGetSymbolAddress((void**)&gg,   g_g);
    cudaGetSymbolAddress((void**)&gcs,  g_gcs);
    cudaGetSymbolAddress((void**)&u,    g_u);
    cudaGetSymbolAddress((void**)&w,    g_wb);
    cudaGetSymbolAddress((void**)&attn, g_attn);
    cudaGetSymbolAddress((void**)&o,    g_o);
    cudaGetSymbolAddress((void**)&x2,   g_x2);
    cudaGetSymbolAddress((void**)&up,   g_up);

    __nv_bfloat16 *hhi, *hlo, *ochi, *oclo, *guhi, *gulo;
    __nv_bfloat16 *w1hi, *w1lo, *wohi, *wolo, *wghi, *wglo, *wuhi, *wulo, *wdhi, *wdlo;
    cudaGetSymbolAddress((void**)&hhi,  b_h_hi);
    cudaGetSymbolAddress((void**)&hlo,  b_h_lo);
    cudaGetSymbolAddress((void**)&ochi, b_oc_hi);
    cudaGetSymbolAddress((void**)&oclo, b_oc_lo);
    cudaGetSymbolAddress((void**)&guhi, b_gu_hi);
    cudaGetSymbolAddress((void**)&gulo, b_gu_lo);
    cudaGetSymbolAddress((void**)&w1hi, b_w1_hi);
    cudaGetSymbolAddress((void**)&w1lo, b_w1_lo);
    cudaGetSymbolAddress((void**)&wohi, b_wo_hi);
    cudaGetSymbolAddress((void**)&wolo, b_wo_lo);
    cudaGetSymbolAddress((void**)&wghi, b_wg_hi);
    cudaGetSymbolAddress((void**)&wglo, b_wg_lo);
    cudaGetSymbolAddress((void**)&wuhi, b_wu_hi);
    cudaGetSymbolAddress((void**)&wulo, b_wu_lo);
    cudaGetSymbolAddress((void**)&wdhi, b_wd_hi);
    cudaGetSymbolAddress((void**)&wdlo, b_wd_lo);

    cudaFuncSetAttribute(prep_kernel, cudaFuncAttributeMaxDynamicSharedMemorySize, (int)sizeof(PrepShm));
    cudaFuncSetAttribute(scan_kernel, cudaFuncAttributeMaxDynamicSharedMemorySize, (int)sizeof(ScanShm));
    const int GSMEM = 3 * GSTAGE;  // 96KB
    cudaFuncSetAttribute(gemm_tc, cudaFuncAttributeMaxDynamicSharedMemorySize, GSMEM);

    // weight conversions
    cvt_hilo<<<(QKVZ_N * DMODEL) / 1024, 256>>>(qkvz_w, w1hi, w1lo, QKVZ_N * DMODEL);
    cvt_hilo<<<(DMODEL * DMODEL) / 1024, 256>>>(out_w,  wohi, wolo, DMODEL * DMODEL);
    cvt_hilo<<<(MDIM * DMODEL) / 1024, 256>>>(gate_w, wghi, wglo, MDIM * DMODEL);
    cvt_hilo<<<(MDIM * DMODEL) / 1024, 256>>>(up_w,   wuhi, wulo, MDIM * DMODEL);
    cvt_hilo<<<(DMODEL * MDIM) / 1024, 256>>>(down_w, wdhi, wdlo, DMODEL * MDIM);

    // 1) h = rms(x, ln1) (+ hi/lo)
    rmsnorm_kernel<<<T_LEN, 256>>>(x, ln1_w, h, hhi, hlo);
    // 2) qkvz = h @ qkvz_w^T ; ba = h @ ba_w^T
    gemm_tc<<<dim3(QKVZ_N / 128, T_LEN / 128), 256, GSMEM>>>(hhi, hlo, w1hi, w1lo, (const float*)0, qkvz, T_LEN, QKVZ_N, DMODEL);
    gemm_n32<<<T_LEN / 32, 256>>>(h, ba_w, ba, DMODEL);
    // 3) conv + silu + l2norm
    conv_kernel<<<dim3(48, T_LEN), 128>>>(qkvz, conv_w, qb, kb, vb);
    // 4) beta, g, gcs
    betag_kernel<<<(NHEAD * T_LEN + 255) / 256, 256>>>(ba, A_log, dt_bias, beta, gg);
    gcs_kernel<<<NHEAD * NCHUNK, 64>>>(gg, gcs);
    // 5) chunk prep
    prep_kernel<<<dim3(NCHUNK, NHEAD), 128, sizeof(PrepShm)>>>(kb, vb, qb, beta, gcs, u, w, attn);
    // 6) scan
    scan_kernel<<<dim3(NHEAD, DHEAD / DVS), 256, sizeof(ScanShm)>>>(qb, kb, w, u, attn, gcs, o);
    // 7) gated norm * silu(z) -> oc hi/lo
    gated_out_kernel<<<dim3(NHEAD, T_LEN), 128>>>(o, qkvz, o_norm_w, ochi, oclo);
    // 8) x2 = x + oc @ out_w^T
    gemm_tc<<<dim3(DMODEL / 128, T_LEN / 128), 256, GSMEM>>>(ochi, oclo, wohi, wolo, x, x2, T_LEN, DMODEL, DMODEL);
    // 9) h2 = rms(x2, ln2)
    rmsnorm_kernel<<<T_LEN, 256>>>(x2, ln2_w, h, hhi, hlo);
    // 10) gate, up GEMMs
    gemm_tc<<<dim3(MDIM / 128, T_LEN / 128), 256, GSMEM>>>(hhi, hlo, wghi, wglo, (const float*)0, qkvz, T_LEN, MDIM, DMODEL);
    gemm_tc<<<dim3(MDIM / 128, T_LEN / 128), 256, GSMEM>>>(hhi, hlo, wuhi, wulo, (const float*)0, up, T_LEN, MDIM, DMODEL);
    // 11) gu = silu(gate) * up -> hi/lo
    glu_kernel<<<(T_LEN * MDIM) / 256, 256>>>(qkvz, up, guhi, gulo);
    // 12) out = x2 + gu @ down_w^T
    gemm_tc<<<dim3(DMODEL / 128, T_LEN / 128), 256, GSMEM>>>(guhi, gulo, wdhi, wdlo, x2, out, T_LEN, DMODEL, MDIM);
}

// round 8
// speedup vs baseline: 2.8397x; 1.1861x over previous
#include <cuda_runtime.h>
#include <cuda_fp16.h>
#include <math.h>
#include <stdint.h>

// ---------------- Problem constants (B=1) ----------------
#define T_LEN   4096
#define DMODEL  2048
#define NHEAD   16
#define DHEAD   128
#define NCHUNK  64
#define CLEN    64
#define QKVZ_N  8192
#define MIX_N   6144
#define MDIM    8192

// ---------------- fp32 scratch ----------------
__device__ float g_h   [T_LEN * DMODEL];
__device__ float g_qkvz[T_LEN * QKVZ_N];
__device__ float g_ba  [T_LEN * 32];
__device__ float g_qb  [NHEAD * T_LEN * DHEAD];
__device__ float g_kb  [NHEAD * T_LEN * DHEAD];
__device__ float g_vb  [NHEAD * T_LEN * DHEAD];
__device__ float g_beta[NHEAD * T_LEN];
__device__ float g_g   [NHEAD * T_LEN];
__device__ float g_gcs [NHEAD * T_LEN];
__device__ float g_u   [NHEAD * T_LEN * DHEAD];
__device__ float g_wb  [NHEAD * T_LEN * DHEAD];
__device__ float g_attn[NHEAD * NCHUNK * CLEN * CLEN];
__device__ float g_o   [NHEAD * T_LEN * DHEAD];
__device__ float g_x2  [T_LEN * DMODEL];
__device__ float g_up  [T_LEN * MDIM];

// ---------------- fp16 operand scratch ----------------
__device__ __half b_h16 [T_LEN * DMODEL];    // activations, single fp16
__device__ __half b_oc16[T_LEN * DMODEL];
__device__ __half b_gu16[T_LEN * MDIM];
__device__ __half b_w1_hi[QKVZ_N * DMODEL];  // weights hi/lo
__device__ __half b_w1_lo[QKVZ_N * DMODEL];
__device__ __half b_wo_hi[DMODEL * DMODEL];
__device__ __half b_wo_lo[DMODEL * DMODEL];
__device__ __half b_wg_hi[MDIM * DMODEL];
__device__ __half b_wg_lo[MDIM * DMODEL];
__device__ __half b_wu_hi[MDIM * DMODEL];
__device__ __half b_wu_lo[MDIM * DMODEL];
__device__ __half b_wd_hi[DMODEL * MDIM];
__device__ __half b_wd_lo[DMODEL * MDIM];

// ---------------- PTX helpers (sm_103-safe) ----------------
__device__ __forceinline__ uint32_t smem_u32(const void* p) {
    uint32_t a;
    asm("{ .reg .u64 t; cvta.to.shared.u64 t, %1; cvt.u32.u64 %0, t; }" : "=r"(a) : "l"(p));
    return a;
}
#define CP_ASYNC16(d,s) asm volatile("cp.async.cg.shared.global [%0], [%1], 16;" :: "r"(d), "l"(s))
#define CP_COMMIT()     asm volatile("cp.async.commit_group;" ::: "memory")
#define CP_WAIT2()      asm volatile("cp.async.wait_group 2;" ::: "memory")
#define CP_WAIT1()      asm volatile("cp.async.wait_group 1;" ::: "memory")
#define CP_WAIT0()      asm volatile("cp.async.wait_group 0;" ::: "memory")

__device__ __forceinline__ void ldsm4(uint32_t addr, uint32_t* o) {
    uint32_t r0, r1, r2, r3;
    asm volatile("ldmatrix.sync.aligned.m8n8.x4.shared.b16 {%0,%1,%2,%3}, [%4];"
        : "=r"(r0), "=r"(r1), "=r"(r2), "=r"(r3) : "r"(addr));
    o[0] = r0; o[1] = r1; o[2] = r2; o[3] = r3;
}

// fp16 m16n8k16 mma, fp32 accum
__device__ __forceinline__ void mma16816(float* d, uint32_t a0, uint32_t a1, uint32_t a2,
                                         uint32_t a3, uint32_t b0, uint32_t b1) {
    float t0 = d[0], t1 = d[1], t2 = d[2], t3 = d[3];
    asm volatile("mma.sync.aligned.m16n8k16.row.col.f32.f16.f16.f32 "
        "{%0,%1,%2,%3},{%4,%5,%6,%7},{%8,%9},{%0,%1,%2,%3};"
        : "+f"(t0), "+f"(t1), "+f"(t2), "+f"(t3)
        : "r"(a0), "r"(a1), "r"(a2), "r"(a3), "r"(b0), "r"(b1));
    d[0] = t0; d[1] = t1; d[2] = t2; d[3] = t3;
}

// ---------------- helpers ----------------
__device__ __forceinline__ float block_reduce_sum(float v, float* shm, int tid, int nthreads) {
    #pragma unroll
    for (int o = 16; o; o >>= 1) v += __shfl_down_sync(0xffffffffu, v, o);
    __syncthreads();
    if ((tid & 31) == 0) shm[tid >> 5] = v;
    __syncthreads();
    int nw = nthreads >> 5;
    float s = (tid < nw) ? shm[tid] : 0.f;
    if (tid < 32) {
        #pragma unroll
        for (int o = 16; o; o >>= 1) s += __shfl_down_sync(0xffffffffu, s, o);
        if (tid == 0) shm[0] = s;
    }
    __syncthreads();
    return shm[0];
}
__device__ __forceinline__ float silu_f(float x) { return x / (1.f + __expf(-x)); }
__device__ __forceinline__ void split_hilo_h(float x, __half& h, __half& l) {
    h = __float2half(x);
    l = __float2half(x - __half2float(h));
}

// ---------------- weight fp32 -> fp16 hi/lo ----------------
__global__ void cvt_hilo(const float* __restrict__ x, __half* __restrict__ hi,
                         __half* __restrict__ lo, int n) {
    int i = (blockIdx.x * blockDim.x + threadIdx.x) * 4;
    if (i >= n) return;
    float4 v = *(const float4*)(x + i);
    __half h0, h1, h2, h3, l0, l1, l2, l3;
    split_hilo_h(v.x, h0, l0); split_hilo_h(v.y, h1, l1);
    split_hilo_h(v.z, h2, l2); split_hilo_h(v.w, h3, l3);
    __half2* hp = (__half2*)(hi + i);
    __half2* lp = (__half2*)(lo + i);
    hp[0] = __halves2half2(h0, h1); hp[1] = __halves2half2(h2, h3);
    lp[0] = __halves2half2(l0, l1); lp[1] = __halves2half2(l2, l3);
}

// ---------------- RMSNorm + fp16 ----------------
__global__ void rmsnorm_kernel(const float* __restrict__ x, const float* __restrict__ w,
                               float* __restrict__ y, __half* __restrict__ y16) {
    int t = blockIdx.x, tid = threadIdx.x;
    __shared__ float shm[32];
    const float* xr = x + (size_t)t * DMODEL;
    float ss = 0.f;
    for (int d = tid; d < DMODEL; d += 256) { float v = xr[d]; ss += v * v; }
    ss = block_reduce_sum(ss, shm, tid, 256);
    float inv = rsqrtf(ss / (float)DMODEL + 1e-5f);
    for (int d = tid; d < DMODEL; d += 256) {
        float v = xr[d] * inv * w[d];
        y[(size_t)t * DMODEL + d] = v;
        y16[(size_t)t * DMODEL + d] = __float2half(v);
    }
}

// ---------------- HMMA GEMM, 2-term weight split ----------------
// C[M,N] = A@B^T (+R). A single fp16; B = Bhi + Blo (fp16 split).
// Per K-stage (BK=32) load A|Bhi|Blo (24KB), run 2 MMA groups (A frags reused).
// 128x128 tile, 8 warps (4x2), warp tile 32x64, 3-buffer cp.async pipeline.
#define GSTAGE 24576   // A 8K | Bhi 8K | Blo 8K
__global__ void __launch_bounds__(256, 2) gemm_tc(
    const __half* __restrict__ A,
    const __half* __restrict__ Bhi, const __half* __restrict__ Blo,
    const float* __restrict__ R, float* __restrict__ C, int M, int N, int K) {
    extern __shared__ char smem_raw[];
    uint32_t sbase = smem_u32(smem_raw);
    int tid = threadIdx.x, lane = tid & 31, warp = tid >> 5;
    int wm = warp >> 1, wn = warp & 1;
    int m0 = blockIdx.y * 128, n0 = blockIdx.x * 128;
    const int TS = K >> 5;

    float acc[2][8][4];
    #pragma unroll
    for (int a = 0; a < 2; a++)
        #pragma unroll
        for (int b = 0; b < 8; b++)
            #pragma unroll
            for (int c = 0; c < 4; c++) acc[a][b][c] = 0.f;

    uint32_t aoff[2][2], boff[4][2];
    {
        int mat = lane >> 3, r = lane & 7;
        #pragma unroll
        for (int mt = 0; mt < 2; mt++) {
            int row = wm * 32 + mt * 16 + ((mat & 1) << 3) + r;
            #pragma unroll
            for (int ks = 0; ks < 2; ks++) {
                int ch = (ks << 1) + (mat >> 1);
                aoff[mt][ks] = row * 64 + ((ch ^ ((row >> 1) & 3)) << 4);
            }
        }
        #pragma unroll
        for (int j = 0; j < 4; j++) {
            int row = wn * 64 + j * 16 + ((mat >> 1) << 3) + r;
            #pragma unroll
            for (int ks = 0; ks < 2; ks++) {
                int ch = (ks << 1) + (mat & 1);
                boff[j][ks] = row * 64 + ((ch ^ ((row >> 1) & 3)) << 4);
            }
        }
    }

    int lrow[2], lc[2]; uint32_t lso[2];
    #pragma unroll
    for (int i = 0; i < 2; i++) {
        int id = (tid << 1) | i;
        lrow[i] = id >> 2; lc[i] = id & 3;
        lso[i] = lrow[i] * 64 + ((lc[i] ^ ((lrow[i] >> 1) & 3)) << 4);
    }

    auto load_stage = [&](int st) {
        int buf = st % 3;
        int k0 = st << 5;
        uint32_t bb = sbase + buf * GSTAGE;
        #pragma unroll
        for (int i = 0; i < 2; i++) {
            size_t aidx = (size_t)(m0 + lrow[i]) * K + k0 + lc[i] * 8;
            size_t bidx = (size_t)(n0 + lrow[i]) * K + k0 + lc[i] * 8;
            CP_ASYNC16(bb + lso[i],         A   + aidx);
            CP_ASYNC16(bb + 8192  + lso[i], Bhi + bidx);
            CP_ASYNC16(bb + 16384 + lso[i], Blo + bidx);
        }
        CP_COMMIT();
    };

    load_stage(0); load_stage(1); load_stage(2);

    for (int st = 0; st < TS; st++) {
        int rem = TS - 1 - st;
        if (rem >= 2) { CP_WAIT2(); } else if (rem == 1) { CP_WAIT1(); } else { CP_WAIT0(); }
        __syncthreads();

        uint32_t stb = sbase + (st % 3) * GSTAGE;
        #pragma unroll
        for (int ks = 0; ks < 2; ks++) {
            uint32_t af[2][4], bf[4][4];
            ldsm4(stb + aoff[0][ks], af[0]);
            ldsm4(stb + aoff[1][ks], af[1]);
            // term0: A * Bhi
            #pragma unroll
            for (int j = 0; j < 4; j++) ldsm4(stb + 8192 + boff[j][ks], bf[j]);
            #pragma unroll
            for (int mt = 0; mt < 2; mt++)
                #pragma unroll
                for (int j = 0; j < 4; j++) {
                    mma16816(&acc[mt][2 * j][0],     af[mt][0], af[mt][1], af[mt][2], af[mt][3], bf[j][0], bf[j][1]);
                    mma16816(&acc[mt][2 * j + 1][0], af[mt][0], af[mt][1], af[mt][2], af[mt][3], bf[j][2], bf[j][3]);
                }
            // term1: A * Blo (A frags reused in registers)
            #pragma unroll
            for (int j = 0; j < 4; j++) ldsm4(stb + 16384 + boff[j][ks], bf[j]);
            #pragma unroll
            for (int mt = 0; mt < 2; mt++)
                #pragma unroll
                for (int j = 0; j < 4; j++) {
                    mma16816(&acc[mt][2 * j][0],     af[mt][0], af[mt][1], af[mt][2], af[mt][3], bf[j][0], bf[j][1]);
                    mma16816(&acc[mt][2 * j + 1][0], af[mt][0], af[mt][1], af[mt][2], af[mt][3], bf[j][2], bf[j][3]);
                }
        }
        __syncthreads();
        if (st + 3 < TS) load_stage(st + 3);
    }

    #pragma unroll
    for (int mt = 0; mt < 2; mt++) {
        #pragma unroll
        for (int nt = 0; nt < 8; nt++) {
            int rr = m0 + wm * 32 + mt * 16 + (lane >> 2);
            int cc = n0 + wn * 64 + nt * 8 + ((lane & 3) << 1);
            float2 v0, v1;
            v0.x = acc[mt][nt][0]; v0.y = acc[mt][nt][1];
            v1.x = acc[mt][nt][2]; v1.y = acc[mt][nt][3];
            if (R != 0) {
                const float2 r0 = *(const float2*)(R + (size_t)rr * N + cc);
                const float2 r1 = *(const float2*)(R + (size_t)(rr + 8) * N + cc);
                v0.x += r0.x; v0.y += r0.y; v1.x += r1.x; v1.y += r1.y;
            }
            *(float2*)(C + (size_t)rr * N + cc) = v0;
            *(float2*)(C + (size_t)(rr + 8) * N + cc) = v1;
        }
    }
}

// ---------------- small-N GEMM for ba ----------------
__global__ void gemm_n32(const float* __restrict__ A, const float* __restrict__ B,
                         float* __restrict__ C, int K) {
    __shared__ float hs[32][65];
    __shared__ float ws[32][65];
    int m0 = blockIdx.x * 32;
    int tid = threadIdx.x;
    int c = tid & 31, r0 = tid >> 5;
    float acc[4] = {0, 0, 0, 0};
    for (int k0 = 0; k0 < K; k0 += 64) {
        __syncthreads();
        for (int idx = tid; idx < 2048; idx += 256) {
            int r = idx >> 6, kk = idx & 63;
            hs[r][kk] = A[(size_t)(m0 + r) * K + k0 + kk];
            ws[r][kk] = B[(size_t)r * K + k0 + kk];
        }
        __syncthreads();
        for (int kk = 0; kk < 64; kk++) {
            float wv = ws[c][kk];
            #pragma unroll
            for (int s = 0; s < 4; s++) acc[s] += hs[r0 + 8 * s][kk] * wv;
        }
    }
    #pragma unroll
    for (int s = 0; s < 4; s++) C[(size_t)(m0 + r0 + 8 * s) * 32 + c] = acc[s];
}

// ---------------- causal conv + silu + l2norm + head split ----------------
__global__ void conv_kernel(const float* __restrict__ qkvz, const float* __restrict__ conv_w,
                            float* __restrict__ qo, float* __restrict__ ko, float* __restrict__ vo) {
    int t = blockIdx.y;
    int wh = blockIdx.x;
    int which = wh >> 4, head = wh & 15;
    int d = threadIdx.x;
    int c = which * 2048 + head * 128 + d;
    float acc = 0.f;
    #pragma unroll
    for (int j = 0; j < 4; j++) {
        int tt = t - 3 + j;
        if (tt >= 0) acc += qkvz[(size_t)tt * QKVZ_N + c] * conv_w[c * 4 + j];
    }
    float s = silu_f(acc);
    size_t oidx = ((size_t)head * T_LEN + t) * DHEAD + d;
    if (which == 2) { vo[oidx] = s; return; }
    __shared__ float shm[32];
    float ss = block_reduce_sum(s * s, shm, d, 128);
    float val = s * rsqrtf(ss + 1e-6f);
    if (which == 0) val *= 0.08838834764831845f;
    (which == 0 ? qo : ko)[oidx] = val;
}

// ---------------- beta / g ----------------
__global__ void betag_kernel(const float* __restrict__ ba, const float* __restrict__ A_log,
                             const float* __restrict__ dt_bias,
                             float* __restrict__ beta, float* __restrict__ g) {
    int idx = blockIdx.x * blockDim.x + threadIdx.x;
    if (idx >= NHEAD * T_LEN) return;
    int t = idx >> 4, h = idx & 15;
    float b = ba[t * 32 + h];
    float a = ba[t * 32 + 16 + h];
    beta[h * T_LEN + t] = 1.f / (1.f + expf(-b));
    float xx = a + dt_bias[h];
    float sp = (xx > 20.f) ? xx : log1pf(expf(xx));
    g[h * T_LEN + t] = -expf(A_log[h]) * sp;
}

// ---------------- within-chunk cumsum of g ----------------
__global__ void gcs_kernel(const float* __restrict__ g, float* __restrict__ gcs) {
    int h = blockIdx.x >> 6, n = blockIdx.x & 63;
    __shared__ float s[64];
    int i = threadIdx.x;
    int base = h * T_LEN + n * 64;
    s[i] = g[base + i];
    __syncthreads();
    for (int off = 1; off < 64; off <<= 1) {
        float v = (i >= off) ? s[i - off] : 0.f;
        __syncthreads();
        s[i] += v;
        __syncthreads();
    }
    gcs[base + i] = s[i];
}

// ---------------- per-chunk prep: A, T=(I+A)^-1, u, w, attn ----------------
struct PrepShm {
    float k[64][128];
    float x[64][128];
    float A[64][64];
    float T[64][64];
    float gcs[64];
    float beta[64];
    float coef[64];
};
extern __shared__ float dyn_smem[];

__global__ void __launch_bounds__(128) prep_kernel(
    const float* __restrict__ gk, const float* __restrict__ gv, const float* __restrict__ gq,
    const float* __restrict__ gbeta, const float* __restrict__ ggcs,
    float* __restrict__ gu, float* __restrict__ gw, float* __restrict__ gattn) {
    PrepShm& S = *(PrepShm*)dyn_smem;
    int n = blockIdx.x, h = blockIdx.y;
    int tid = threadIdx.x;
    int base = h * T_LEN + n * 64;

    if (tid < 64) {
        S.gcs[tid]  = ggcs[base + tid];
        S.beta[tid] = gbeta[base + tid];
    }
    for (int idx = tid; idx < 64 * 128; idx += 128) {
        int i = idx >> 7, d = idx & 127;
        S.k[i][d] = gk[(size_t)(base + i) * DHEAD + d];
    }
    __syncthreads();
    for (int idx = tid; idx < 64 * 128; idx += 128) {
        int i = idx >> 7, d = idx & 127;
        S.x[i][d] = gv[(size_t)(base + i) * DHEAD + d] * S.beta[i];
    }
    for (int idx = tid; idx < 4096; idx += 128) {
        int i = idx >> 6, j = idx & 63;
        float val = 0.f;
        if (j < i) {
            float acc = 0.f;
            #pragma unroll 8
            for (int d = 0; d < 128; d++) {
                int dd = (d + tid) & 127;
                acc += S.k[i][dd] * S.k[j][dd];
            }
            val = acc * S.beta[i] * __expf(S.gcs[i] - S.gcs[j]);
        }
        S.A[i][j] = val;
    }
    __syncthreads();
    if (tid < 64) S.T[0][tid] = (tid == 0) ? 1.f : 0.f;
    __syncthreads();
    for (int i = 1; i < 64; i++) {
        if (tid < 64) {
            float acc = 0.f;
            for (int j = 0; j < i; j++) acc += S.A[i][j] * S.T[j][tid];
            S.T[i][tid] = ((tid == i) ? 1.f : 0.f) - acc;
        }
        __syncthreads();
    }
    if (tid < 64) S.coef[tid] = S.beta[tid] * __expf(S.gcs[tid]);
    __syncthreads();
    for (int idx = tid; idx < 64 * 128; idx += 128) {
        int i = idx >> 7, d = idx & 127;
        float au = 0.f, aw = 0.f;
        for (int j = 0; j <= i; j++) {
            float tij = S.T[i][j];
            au += tij * S.x[j][d];
            aw += tij * S.coef[j] * S.k[j][d];
        }
        gu[(size_t)(base + i) * DHEAD + d] = au;
        gw[(size_t)(base + i) * DHEAD + d] = aw;
    }
    __syncthreads();
    for (int idx = tid; idx < 64 * 128; idx += 128) {
        int i = idx >> 7, d = idx & 127;
        S.x[i][d] = gq[(size_t)(base + i) * DHEAD + d];
    }
    __syncthreads();
    float* attn_out = gattn + ((size_t)(h * 64 + n)) * 64 * 64;
    for (int idx = tid; idx < 4096; idx += 128) {
        int i = idx >> 6, j = idx & 63;
        float val = 0.f;
        if (j <= i) {
            float acc = 0.f;
            #pragma unroll 8
            for (int d = 0; d < 128; d++) {
                int dd = (d + tid) & 127;
                acc += S.x[i][dd] * S.k[j][dd];
            }
            val = acc * __expf(S.gcs[i] - S.gcs[j]);
        }
        attn_out[i * 64 + j] = val;
    }
}

// ---------------- sequential scan ----------------
#define DVS 16
struct ScanShm {
    float S[128][DVS];
    float w[64][132];
    float q[64][132];
    float k[64][132];
    float attn[64][68];
    float u[64][DVS];
    float vn[64][DVS];
    float gcs[64];
    float ex[64];
};

__global__ void __launch_bounds__(256) scan_kernel(
    const float* __restrict__ gq, const float* __restrict__ gk, const float* __restrict__ gw,
    const float* __restrict__ gu, const float* __restrict__ gattn, const float* __restrict__ ggcs,
    float* __restrict__ go) {
    ScanShm& S = *(ScanShm*)dyn_smem;
    int h = blockIdx.x;
    int dv0 = blockIdx.y * DVS;
    int tid = threadIdx.x;

    for (int idx = tid; idx < 128 * DVS; idx += 256) S.S[idx >> 4][idx & 15] = 0.f;

    for (int n = 0; n < NCHUNK; n++) {
        int base = h * T_LEN + n * 64;
        if (tid < 64) S.gcs[tid] = ggcs[base + tid];
        for (int idx = tid; idx < 64 * 128; idx += 256) {
            int i = idx >> 7, d = idx & 127;
            size_t gidx = (size_t)(base + i) * DHEAD + d;
            S.w[i][d] = gw[gidx];
            S.q[i][d] = gq[gidx];
            S.k[i][d] = gk[gidx];
        }
        const float* ap = gattn + ((size_t)(h * 64 + n)) * 64 * 64;
        for (int idx = tid; idx < 4096; idx += 256) S.attn[idx >> 6][idx & 63] = ap[idx];
        for (int idx = tid; idx < 64 * DVS; idx += 256) {
            int i = idx >> 4, dv = idx & 15;
            S.u[i][dv] = gu[(size_t)(base + i) * DHEAD + dv0 + dv];
        }
        __syncthreads();
        if (tid < 64) S.ex[tid] = __expf(S.gcs[63] - S.gcs[tid]);

        int i = tid >> 2, dvb = (tid & 3) * 4;
        {
            float4 uv = *(const float4*)&S.u[i][dvb];
            float a0 = uv.x, a1 = uv.y, a2 = uv.z, a3 = uv.w;
            for (int d = 0; d < 128; d++) {
                float wv = S.w[i][d];
                float4 sv = *(const float4*)&S.S[d][dvb];
                a0 -= wv * sv.x; a1 -= wv * sv.y; a2 -= wv * sv.z; a3 -= wv * sv.w;
            }
            float4 r; r.x = a0; r.y = a1; r.z = a2; r.w = a3;
            *(float4*)&S.vn[i][dvb] = r;
        }
        __syncthreads();
        {
            float a0 = 0, a1 = 0, a2 = 0, a3 = 0;
            for (int d = 0; d < 128; d++) {
                float qv = S.q[i][d];
                float4 sv = *(const float4*)&S.S[d][dvb];
                a0 += qv * sv.x; a1 += qv * sv.y; a2 += qv * sv.z; a3 += qv * sv.w;
            }
            float eg = __expf(S.gcs[i]);
            a0 *= eg; a1 *= eg; a2 *= eg; a3 *= eg;
            for (int j = 0; j <= i; j++) {
                float av = S.attn[i][j];
                float4 vv = *(const float4*)&S.vn[j][dvb];
                a0 += av * vv.x; a1 += av * vv.y; a2 += av * vv.z; a3 += av * vv.w;
            }
            float4 r; r.x = a0; r.y = a1; r.z = a2; r.w = a3;
            *(float4*)(go + (size_t)(base + i) * DHEAD + dv0 + dvb) = r;
        }
        __syncthreads();
        {
            float gle = __expf(S.gcs[63]);
            #pragma unroll
            for (int r = 0; r < 2; r++) {
                int qi = tid + 256 * r;
                int d = qi >> 2, db = (qi & 3) * 4;
                float4 sv = *(const float4*)&S.S[d][db];
                float a0 = sv.x * gle, a1 = sv.y * gle, a2 = sv.z * gle, a3 = sv.w * gle;
                for (int ii = 0; ii < 64; ii++) {
                    float kk = S.k[ii][d] * S.ex[ii];
                    float4 vv = *(const float4*)&S.vn[ii][db];
                    a0 += kk * vv.x; a1 += kk * vv.y; a2 += kk * vv.z; a3 += kk * vv.w;
                }
                float4 w4; w4.x = a0; w4.y = a1; w4.z = a2; w4.w = a3;
                *(float4*)&S.S[d][db] = w4;
            }
        }
        __syncthreads();
    }
}

// ---------------- gated RMSNorm * silu(z) -> fp16 ----------------
__global__ void gated_out_kernel(const float* __restrict__ go, const float* __restrict__ qkvz,
                                 const float* __restrict__ onw, __half* __restrict__ oc16) {
    int h = blockIdx.x, t = blockIdx.y, d = threadIdx.x;
    __shared__ float shm[32];
    float v = go[((size_t)h * T_LEN + t) * DHEAD + d];
    float ss = block_reduce_sum(v * v, shm, d, 128);
    float inv = rsqrtf(ss / 128.f + 1e-5f);
    float z = qkvz[(size_t)t * QKVZ_N + MIX_N + h * 128 + d];
    float res = v * inv * onw[d] * silu_f(z);
    oc16[(size_t)t * DMODEL + h * 128 + d] = __float2half(res);
}

// ---------------- GLU -> fp16 ----------------
__global__ void glu_kernel(const float* __restrict__ gate, const float* __restrict__ up,
                           __half* __restrict__ gu16) {
    int i = blockIdx.x * blockDim.x + threadIdx.x;
    float v = silu_f(gate[i]) * up[i];
    gu16[i] = __float2half(v);
}

// ---------------- host launch ----------------
extern "C" void kernel_launch(void* const* d_in, const int* in_sizes, int n_in,
                              void* d_out, int out_size) {
    const float* x       = (const float*)d_in[0];
    const float* ln1_w   = (const float*)d_in[2];
    const float* qkvz_w  = (const float*)d_in[3];
    const float* ba_w    = (const float*)d_in[4];
    const float* conv_w  = (const float*)d_in[5];
    const float* A_log   = (const float*)d_in[6];
    const float* dt_bias = (const float*)d_in[7];
    const float* o_norm_w= (const float*)d_in[8];
    const float* out_w   = (const float*)d_in[9];
    const float* ln2_w   = (const float*)d_in[10];
    const float* gate_w  = (const float*)d_in[11];
    const float* up_w    = (const float*)d_in[12];
    const float* down_w  = (const float*)d_in[13];
    float* out = (float*)d_out;

    float *h, *qkvz, *ba, *qb, *kb, *vb, *beta, *gg, *gcs, *u, *w, *attn, *o, *x2, *up;
    cudaGetSymbolAddress((void**)&h,    g_h);
    cudaGetSymbolAddress((void**)&qkvz, g_qkvz);
    cudaGetSymbolAddress((void**)&ba,   g_ba);
    cudaGetSymbolAddress((void**)&qb,   g_qb);
    cudaGetSymbolAddress((void**)&kb,   g_kb);
    cudaGetSymbolAddress((void**)&vb,   g_vb);
    cudaGetSymbolAddress((void**)&beta, g_beta);
    cudaGetSymbolAddress((void**)&gg,   g_g);
    cudaGetSymbolAddress((void**)&gcs,  g_gcs);
    cudaGetSymbolAddress((void**)&u,    g_u);
    cudaGetSymbolAddress((void**)&w,    g_wb);
    cudaGetSymbolAddress((void**)&attn, g_attn);
    cudaGetSymbolAddress((void**)&o,    g_o);
    cudaGetSymbolAddress((void**)&x2,   g_x2);
    cudaGetSymbolAddress((void**)&up,   g_up);

    __half *h16, *oc16, *gu16;
    __half *w1hi, *w1lo, *wohi, *wolo, *wghi, *wglo, *wuhi, *wulo, *wdhi, *wdlo;
    cudaGetSymbolAddress((void**)&h16,  b_h16);
    cudaGetSymbolAddress((void**)&oc16, b_oc16);
    cudaGetSymbolAddress((void**)&gu16, b_gu16);
    cudaGetSymbolAddress((void**)&w1hi, b_w1_hi);
    cudaGetSymbolAddress((void**)&w1lo, b_w1_lo);
    cudaGetSymbolAddress((void**)&wohi, b_wo_hi);
    cudaGetSymbolAddress((void**)&wolo, b_wo_lo);
    cudaGetSymbolAddress((void**)&wghi, b_wg_hi);
    cudaGetSymbolAddress((void**)&wglo, b_wg_lo);
    cudaGetSymbolAddress((void**)&wuhi, b_wu_hi);
    cudaGetSymbolAddress((void**)&wulo, b_wu_lo);
    cudaGetSymbolAddress((void**)&wdhi, b_wd_hi);
    cudaGetSymbolAddress((void**)&wdlo, b_wd_lo);

    cudaFuncSetAttribute(prep_kernel, cudaFuncAttributeMaxDynamicSharedMemorySize, (int)sizeof(PrepShm));
    cudaFuncSetAttribute(scan_kernel, cudaFuncAttributeMaxDynamicSharedMemorySize, (int)sizeof(ScanShm));
    const int GSMEM = 3 * GSTAGE;  // 72KB
    cudaFuncSetAttribute(gemm_tc, cudaFuncAttributeMaxDynamicSharedMemorySize, GSMEM);

    // weight conversions
    cvt_hilo<<<(QKVZ_N * DMODEL) / 1024, 256>>>(qkvz_w, w1hi, w1lo, QKVZ_N * DMODEL);
    cvt_hilo<<<(DMODEL * DMODEL) / 1024, 256>>>(out_w,  wohi, wolo, DMODEL * DMODEL);
    cvt_hilo<<<(MDIM * DMODEL) / 1024, 256>>>(gate_w, wghi, wglo, MDIM * DMODEL);
    cvt_hilo<<<(MDIM * DMODEL) / 1024, 256>>>(up_w,   wuhi, wulo, MDIM * DMODEL);
    cvt_hilo<<<(DMODEL * MDIM) / 1024, 256>>>(down_w, wdhi, wdlo, DMODEL * MDIM);

    // 1) h = rms(x, ln1) (+ fp16)
    rmsnorm_kernel<<<T_LEN, 256>>>(x, ln1_w, h, h16);
    // 2) qkvz = h @ qkvz_w^T ; ba = h @ ba_w^T
    gemm_tc<<<dim3(QKVZ_N / 128, T_LEN / 128), 256, GSMEM>>>(h16, w1hi, w1lo, (const float*)0, qkvz, T_LEN, QKVZ_N, DMODEL);
    gemm_n32<<<T_LEN / 32, 256>>>(h, ba_w, ba, DMODEL);
    // 3) conv + silu + l2norm
    conv_kernel<<<dim3(48, T_LEN), 128>>>(qkvz, conv_w, qb, kb, vb);
    // 4) beta, g, gcs
    betag_kernel<<<(NHEAD * T_LEN + 255) / 256, 256>>>(ba, A_log, dt_bias, beta, gg);
    gcs_kernel<<<NHEAD * NCHUNK, 64>>>(gg, gcs);
    // 5) chunk prep
    prep_kernel<<<dim3(NCHUNK, NHEAD), 128, sizeof(PrepShm)>>>(kb, vb, qb, beta, gcs, u, w, attn);
    // 6) scan
    scan_kernel<<<dim3(NHEAD, DHEAD / DVS), 256, sizeof(ScanShm)>>>(qb, kb, w, u, attn, gcs, o);
    // 7) gated norm * silu(z) -> oc16
    gated_out_kernel<<<dim3(NHEAD, T_LEN), 128>>>(o, qkvz, o_norm_w, oc16);
    // 8) x2 = x + oc @ out_w^T
    gemm_tc<<<dim3(DMODEL / 128, T_LEN / 128), 256, GSMEM>>>(oc16, wohi, wolo, x, x2, T_LEN, DMODEL, DMODEL);
    // 9) h2 = rms(x2, ln2)
    rmsnorm_kernel<<<T_LEN, 256>>>(x2, ln2_w, h, h16);
    // 10) gate, up GEMMs
    gemm_tc<<<dim3(MDIM / 128, T_LEN / 128), 256, GSMEM>>>(h16, wghi, wglo, (const float*)0, qkvz, T_LEN, MDIM, DMODEL);
    gemm_tc<<<dim3(MDIM / 128, T_LEN / 128), 256, GSMEM>>>(h16, wuhi, wulo, (const float*)0, up, T_LEN, MDIM, DMODEL);
    // 11) gu = silu(gate) * up -> fp16
    glu_kernel<<<(T_LEN * MDIM) / 256, 256>>>(qkvz, up, gu16);
    // 12) out = x2 + gu @ down_w^T
    gemm_tc<<<dim3(DMODEL / 128, T_LEN / 128), 256, GSMEM>>>(gu16, wdhi, wdlo, x2, out, T_LEN, DMODEL, MDIM);
}

// round 9
// speedup vs baseline: 3.8451x; 1.3540x over previous
#include <cuda_runtime.h>
#include <cuda_fp16.h>
#include <math.h>
#include <stdint.h>

// ---------------- Problem constants (B=1) ----------------
#define T_LEN   4096
#define DMODEL  2048
#define NHEAD   16
#define DHEAD   128
#define NCHUNK  64
#define CLEN    64
#define QKVZ_N  8192
#define MIX_N   6144
#define MDIM    8192

// ---------------- fp32 scratch ----------------
__device__ float g_h   [T_LEN * DMODEL];
__device__ float g_qkvz[T_LEN * QKVZ_N];
__device__ float g_ba  [T_LEN * 32];
__device__ float g_qb  [NHEAD * T_LEN * DHEAD];
__device__ float g_kb  [NHEAD * T_LEN * DHEAD];
__device__ float g_vb  [NHEAD * T_LEN * DHEAD];
__device__ float g_beta[NHEAD * T_LEN];
__device__ float g_g   [NHEAD * T_LEN];
__device__ float g_gcs [NHEAD * T_LEN];
__device__ float g_u   [NHEAD * T_LEN * DHEAD];
__device__ float g_wb  [NHEAD * T_LEN * DHEAD];
__device__ float g_attn[NHEAD * NCHUNK * CLEN * CLEN];
__device__ float g_o   [NHEAD * T_LEN * DHEAD];
__device__ float g_x2  [T_LEN * DMODEL];
__device__ float g_up  [T_LEN * MDIM];

// ---------------- fp16 operand scratch ----------------
__device__ __half b_h16 [T_LEN * DMODEL];
__device__ __half b_oc16[T_LEN * DMODEL];
__device__ __half b_gu16[T_LEN * MDIM];
__device__ __half b_w1 [QKVZ_N * DMODEL];
__device__ __half b_wo [DMODEL * DMODEL];
__device__ __half b_wg [MDIM * DMODEL];
__device__ __half b_wu [MDIM * DMODEL];
__device__ __half b_wd [DMODEL * MDIM];

// ---------------- PTX helpers (sm_103-safe) ----------------
__device__ __forceinline__ uint32_t smem_u32(const void* p) {
    uint32_t a;
    asm("{ .reg .u64 t; cvta.to.shared.u64 t, %1; cvt.u32.u64 %0, t; }" : "=r"(a) : "l"(p));
    return a;
}
#define CP_ASYNC16(d,s) asm volatile("cp.async.cg.shared.global [%0], [%1], 16;" :: "r"(d), "l"(s))
#define CP_COMMIT()     asm volatile("cp.async.commit_group;" ::: "memory")
#define CP_WAIT2()      asm volatile("cp.async.wait_group 2;" ::: "memory")
#define CP_WAIT1()      asm volatile("cp.async.wait_group 1;" ::: "memory")
#define CP_WAIT0()      asm volatile("cp.async.wait_group 0;" ::: "memory")

__device__ __forceinline__ void ldsm4(uint32_t addr, uint32_t* o) {
    uint32_t r0, r1, r2, r3;
    asm volatile("ldmatrix.sync.aligned.m8n8.x4.shared.b16 {%0,%1,%2,%3}, [%4];"
        : "=r"(r0), "=r"(r1), "=r"(r2), "=r"(r3) : "r"(addr));
    o[0] = r0; o[1] = r1; o[2] = r2; o[3] = r3;
}

__device__ __forceinline__ void mma16816(float* d, uint32_t a0, uint32_t a1, uint32_t a2,
                                         uint32_t a3, uint32_t b0, uint32_t b1) {
    float t0 = d[0], t1 = d[1], t2 = d[2], t3 = d[3];
    asm volatile("mma.sync.aligned.m16n8k16.row.col.f32.f16.f16.f32 "
        "{%0,%1,%2,%3},{%4,%5,%6,%7},{%8,%9},{%0,%1,%2,%3};"
        : "+f"(t0), "+f"(t1), "+f"(t2), "+f"(t3)
        : "r"(a0), "r"(a1), "r"(a2), "r"(a3), "r"(b0), "r"(b1));
    d[0] = t0; d[1] = t1; d[2] = t2; d[3] = t3;
}

// ---------------- helpers ----------------
__device__ __forceinline__ float block_reduce_sum(float v, float* shm, int tid, int nthreads) {
    #pragma unroll
    for (int o = 16; o; o >>= 1) v += __shfl_down_sync(0xffffffffu, v, o);
    __syncthreads();
    if ((tid & 31) == 0) shm[tid >> 5] = v;
    __syncthreads();
    int nw = nthreads >> 5;
    float s = (tid < nw) ? shm[tid] : 0.f;
    if (tid < 32) {
        #pragma unroll
        for (int o = 16; o; o >>= 1) s += __shfl_down_sync(0xffffffffu, s, o);
        if (tid == 0) shm[0] = s;
    }
    __syncthreads();
    return shm[0];
}
__device__ __forceinline__ float silu_f(float x) { return x / (1.f + __expf(-x)); }

// ---------------- weight fp32 -> fp16 ----------------
__global__ void cvt16(const float* __restrict__ x, __half* __restrict__ y, int n) {
    int i = (blockIdx.x * blockDim.x + threadIdx.x) * 4;
    if (i >= n) return;
    float4 v = *(const float4*)(x + i);
    __half2* yp = (__half2*)(y + i);
    yp[0] = __halves2half2(__float2half(v.x), __float2half(v.y));
    yp[1] = __halves2half2(__float2half(v.z), __float2half(v.w));
}

// ---------------- RMSNorm + fp16 ----------------
__global__ void rmsnorm_kernel(const float* __restrict__ x, const float* __restrict__ w,
                               float* __restrict__ y, __half* __restrict__ y16) {
    int t = blockIdx.x, tid = threadIdx.x;
    __shared__ float shm[32];
    const float* xr = x + (size_t)t * DMODEL;
    float ss = 0.f;
    for (int d = tid; d < DMODEL; d += 256) { float v = xr[d]; ss += v * v; }
    ss = block_reduce_sum(ss, shm, tid, 256);
    float inv = rsqrtf(ss / (float)DMODEL + 1e-5f);
    for (int d = tid; d < DMODEL; d += 256) {
        float v = xr[d] * inv * w[d];
        y[(size_t)t * DMODEL + d] = v;
        y16[(size_t)t * DMODEL + d] = __float2half(v);
    }
}

// ---------------- HMMA GEMM, single fp16 term ----------------
// C[M,N] = A@B^T (+R). 128x128 tile, BK=32, 8 warps (4x2), warp tile 32x64,
// 3-buffer cp.async pipeline. Row 64B, swizzle c ^= (row>>1)&3.
#define GSTAGE 16384   // A 8K | B 8K
__global__ void __launch_bounds__(256, 2) gemm_tc(
    const __half* __restrict__ A, const __half* __restrict__ B,
    const float* __restrict__ R, float* __restrict__ C, int M, int N, int K) {
    extern __shared__ char smem_raw[];
    uint32_t sbase = smem_u32(smem_raw);
    int tid = threadIdx.x, lane = tid & 31, warp = tid >> 5;
    int wm = warp >> 1, wn = warp & 1;
    int m0 = blockIdx.y * 128, n0 = blockIdx.x * 128;
    const int TS = K >> 5;

    float acc[2][8][4];
    #pragma unroll
    for (int a = 0; a < 2; a++)
        #pragma unroll
        for (int b = 0; b < 8; b++)
            #pragma unroll
            for (int c = 0; c < 4; c++) acc[a][b][c] = 0.f;

    uint32_t aoff[2][2], boff[4][2];
    {
        int mat = lane >> 3, r = lane & 7;
        #pragma unroll
        for (int mt = 0; mt < 2; mt++) {
            int row = wm * 32 + mt * 16 + ((mat & 1) << 3) + r;
            #pragma unroll
            for (int ks = 0; ks < 2; ks++) {
                int ch = (ks << 1) + (mat >> 1);
                aoff[mt][ks] = row * 64 + ((ch ^ ((row >> 1) & 3)) << 4);
            }
        }
        #pragma unroll
        for (int j = 0; j < 4; j++) {
            int row = wn * 64 + j * 16 + ((mat >> 1) << 3) + r;
            #pragma unroll
            for (int ks = 0; ks < 2; ks++) {
                int ch = (ks << 1) + (mat & 1);
                boff[j][ks] = 8192 + row * 64 + ((ch ^ ((row >> 1) & 3)) << 4);
            }
        }
    }

    int lrow[2], lc[2]; uint32_t lso[2];
    #pragma unroll
    for (int i = 0; i < 2; i++) {
        int id = (tid << 1) | i;
        lrow[i] = id >> 2; lc[i] = id & 3;
        lso[i] = lrow[i] * 64 + ((lc[i] ^ ((lrow[i] >> 1) & 3)) << 4);
    }

    auto load_stage = [&](int st) {
        int buf = st % 3;
        int k0 = st << 5;
        uint32_t bb = sbase + buf * GSTAGE;
        #pragma unroll
        for (int i = 0; i < 2; i++) {
            CP_ASYNC16(bb + lso[i],        A + (size_t)(m0 + lrow[i]) * K + k0 + lc[i] * 8);
            CP_ASYNC16(bb + 8192 + lso[i], B + (size_t)(n0 + lrow[i]) * K + k0 + lc[i] * 8);
        }
        CP_COMMIT();
    };

    load_stage(0); load_stage(1); load_stage(2);

    for (int st = 0; st < TS; st++) {
        int rem = TS - 1 - st;
        if (rem >= 2) { CP_WAIT2(); } else if (rem == 1) { CP_WAIT1(); } else { CP_WAIT0(); }
        __syncthreads();

        uint32_t stb = sbase + (st % 3) * GSTAGE;
        #pragma unroll
        for (int ks = 0; ks < 2; ks++) {
            uint32_t af[2][4], bf[4][4];
            ldsm4(stb + aoff[0][ks], af[0]);
            ldsm4(stb + aoff[1][ks], af[1]);
            #pragma unroll
            for (int j = 0; j < 4; j++) ldsm4(stb + boff[j][ks], bf[j]);
            #pragma unroll
            for (int mt = 0; mt < 2; mt++)
                #pragma unroll
                for (int j = 0; j < 4; j++) {
                    mma16816(&acc[mt][2 * j][0],     af[mt][0], af[mt][1], af[mt][2], af[mt][3], bf[j][0], bf[j][1]);
                    mma16816(&acc[mt][2 * j + 1][0], af[mt][0], af[mt][1], af[mt][2], af[mt][3], bf[j][2], bf[j][3]);
                }
        }
        __syncthreads();
        if (st + 3 < TS) load_stage(st + 3);
    }

    #pragma unroll
    for (int mt = 0; mt < 2; mt++) {
        #pragma unroll
        for (int nt = 0; nt < 8; nt++) {
            int rr = m0 + wm * 32 + mt * 16 + (lane >> 2);
            int cc = n0 + wn * 64 + nt * 8 + ((lane & 3) << 1);
            float2 v0, v1;
            v0.x = acc[mt][nt][0]; v0.y = acc[mt][nt][1];
            v1.x = acc[mt][nt][2]; v1.y = acc[mt][nt][3];
            if (R != 0) {
                const float2 r0 = *(const float2*)(R + (size_t)rr * N + cc);
                const float2 r1 = *(const float2*)(R + (size_t)(rr + 8) * N + cc);
                v0.x += r0.x; v0.y += r0.y; v1.x += r1.x; v1.y += r1.y;
            }
            *(float2*)(C + (size_t)rr * N + cc) = v0;
            *(float2*)(C + (size_t)(rr + 8) * N + cc) = v1;
        }
    }
}

// ---------------- small-N GEMM for ba ----------------
__global__ void gemm_n32(const float* __restrict__ A, const float* __restrict__ B,
                         float* __restrict__ C, int K) {
    __shared__ float hs[32][65];
    __shared__ float ws[32][65];
    int m0 = blockIdx.x * 32;
    int tid = threadIdx.x;
    int c = tid & 31, r0 = tid >> 5;
    float acc[4] = {0, 0, 0, 0};
    for (int k0 = 0; k0 < K; k0 += 64) {
        __syncthreads();
        for (int idx = tid; idx < 2048; idx += 256) {
            int r = idx >> 6, kk = idx & 63;
            hs[r][kk] = A[(size_t)(m0 + r) * K + k0 + kk];
            ws[r][kk] = B[(size_t)r * K + k0 + kk];
        }
        __syncthreads();
        for (int kk = 0; kk < 64; kk++) {
            float wv = ws[c][kk];
            #pragma unroll
            for (int s = 0; s < 4; s++) acc[s] += hs[r0 + 8 * s][kk] * wv;
        }
    }
    #pragma unroll
    for (int s = 0; s < 4; s++) C[(size_t)(m0 + r0 + 8 * s) * 32 + c] = acc[s];
}

// ---------------- causal conv + silu + l2norm + head split ----------------
__global__ void conv_kernel(const float* __restrict__ qkvz, const float* __restrict__ conv_w,
                            float* __restrict__ qo, float* __restrict__ ko, float* __restrict__ vo) {
    int t = blockIdx.y;
    int wh = blockIdx.x;
    int which = wh >> 4, head = wh & 15;
    int d = threadIdx.x;
    int c = which * 2048 + head * 128 + d;
    float acc = 0.f;
    #pragma unroll
    for (int j = 0; j < 4; j++) {
        int tt = t - 3 + j;
        if (tt >= 0) acc += qkvz[(size_t)tt * QKVZ_N + c] * conv_w[c * 4 + j];
    }
    float s = silu_f(acc);
    size_t oidx = ((size_t)head * T_LEN + t) * DHEAD + d;
    if (which == 2) { vo[oidx] = s; return; }
    __shared__ float shm[32];
    float ss = block_reduce_sum(s * s, shm, d, 128);
    float val = s * rsqrtf(ss + 1e-6f);
    if (which == 0) val *= 0.08838834764831845f;
    (which == 0 ? qo : ko)[oidx] = val;
}

// ---------------- beta / g ----------------
__global__ void betag_kernel(const float* __restrict__ ba, const float* __restrict__ A_log,
                             const float* __restrict__ dt_bias,
                             float* __restrict__ beta, float* __restrict__ g) {
    int idx = blockIdx.x * blockDim.x + threadIdx.x;
    if (idx >= NHEAD * T_LEN) return;
    int t = idx >> 4, h = idx & 15;
    float b = ba[t * 32 + h];
    float a = ba[t * 32 + 16 + h];
    beta[h * T_LEN + t] = 1.f / (1.f + expf(-b));
    float xx = a + dt_bias[h];
    float sp = (xx > 20.f) ? xx : log1pf(expf(xx));
    g[h * T_LEN + t] = -expf(A_log[h]) * sp;
}

// ---------------- within-chunk cumsum of g ----------------
__global__ void gcs_kernel(const float* __restrict__ g, float* __restrict__ gcs) {
    int h = blockIdx.x >> 6, n = blockIdx.x & 63;
    __shared__ float s[64];
    int i = threadIdx.x;
    int base = h * T_LEN + n * 64;
    s[i] = g[base + i];
    __syncthreads();
    for (int off = 1; off < 64; off <<= 1) {
        float v = (i >= off) ? s[i - off] : 0.f;
        __syncthreads();
        s[i] += v;
        __syncthreads();
    }
    gcs[base + i] = s[i];
}

// ---------------- per-chunk prep: A, T=(I+A)^-1, u, w, attn ----------------
struct PrepShm {
    float k[64][128];
    float x[64][128];
    float A[64][64];
    float T[64][64];
    float gcs[64];
    float beta[64];
    float coef[64];
};
extern __shared__ float dyn_smem[];

__global__ void __launch_bounds__(128) prep_kernel(
    const float* __restrict__ gk, const float* __restrict__ gv, const float* __restrict__ gq,
    const float* __restrict__ gbeta, const float* __restrict__ ggcs,
    float* __restrict__ gu, float* __restrict__ gw, float* __restrict__ gattn) {
    PrepShm& S = *(PrepShm*)dyn_smem;
    int n = blockIdx.x, h = blockIdx.y;
    int tid = threadIdx.x;
    int base = h * T_LEN + n * 64;

    if (tid < 64) {
        S.gcs[tid]  = ggcs[base + tid];
        S.beta[tid] = gbeta[base + tid];
    }
    for (int idx = tid; idx < 64 * 128; idx += 128) {
        int i = idx >> 7, d = idx & 127;
        S.k[i][d] = gk[(size_t)(base + i) * DHEAD + d];
    }
    __syncthreads();
    for (int idx = tid; idx < 64 * 128; idx += 128) {
        int i = idx >> 7, d = idx & 127;
        S.x[i][d] = gv[(size_t)(base + i) * DHEAD + d] * S.beta[i];
    }
    for (int idx = tid; idx < 4096; idx += 128) {
        int i = idx >> 6, j = idx & 63;
        float val = 0.f;
        if (j < i) {
            float acc = 0.f;
            #pragma unroll 8
            for (int d = 0; d < 128; d++) {
                int dd = (d + tid) & 127;
                acc += S.k[i][dd] * S.k[j][dd];
            }
            val = acc * S.beta[i] * __expf(S.gcs[i] - S.gcs[j]);
        }
        S.A[i][j] = val;
    }
    __syncthreads();
    if (tid < 64) S.T[0][tid] = (tid == 0) ? 1.f : 0.f;
    __syncthreads();
    for (int i = 1; i < 64; i++) {
        if (tid < 64) {
            float acc = 0.f;
            for (int j = 0; j < i; j++) acc += S.A[i][j] * S.T[j][tid];
            S.T[i][tid] = ((tid == i) ? 1.f : 0.f) - acc;
        }
        __syncthreads();
    }
    if (tid < 64) S.coef[tid] = S.beta[tid] * __expf(S.gcs[tid]);
    __syncthreads();
    for (int idx = tid; idx < 64 * 128; idx += 128) {
        int i = idx >> 7, d = idx & 127;
        float au = 0.f, aw = 0.f;
        for (int j = 0; j <= i; j++) {
            float tij = S.T[i][j];
            au += tij * S.x[j][d];
            aw += tij * S.coef[j] * S.k[j][d];
        }
        gu[(size_t)(base + i) * DHEAD + d] = au;
        gw[(size_t)(base + i) * DHEAD + d] = aw;
    }
    __syncthreads();
    for (int idx = tid; idx < 64 * 128; idx += 128) {
        int i = idx >> 7, d = idx & 127;
        S.x[i][d] = gq[(size_t)(base + i) * DHEAD + d];
    }
    __syncthreads();
    float* attn_out = gattn + ((size_t)(h * 64 + n)) * 64 * 64;
    for (int idx = tid; idx < 4096; idx += 128) {
        int i = idx >> 6, j = idx & 63;
        float val = 0.f;
        if (j <= i) {
            float acc = 0.f;
            #pragma unroll 8
            for (int d = 0; d < 128; d++) {
                int dd = (d + tid) & 127;
                acc += S.x[i][dd] * S.k[j][dd];
            }
            val = acc * __expf(S.gcs[i] - S.gcs[j]);
        }
        attn_out[i * 64 + j] = val;
    }
}

// ---------------- sequential scan ----------------
#define DVS 16
struct ScanShm {
    float S[128][DVS];
    float w[64][132];
    float q[64][132];
    float k[64][132];
    float attn[64][68];
    float u[64][DVS];
    float vn[64][DVS];
    float gcs[64];
    float ex[64];
};

__global__ void __launch_bounds__(256) scan_kernel(
    const float* __restrict__ gq, const float* __restrict__ gk, const float* __restrict__ gw,
    const float* __restrict__ gu, const float* __restrict__ gattn, const float* __restrict__ ggcs,
    float* __restrict__ go) {
    ScanShm& S = *(ScanShm*)dyn_smem;
    int h = blockIdx.x;
    int dv0 = blockIdx.y * DVS;
    int tid = threadIdx.x;

    for (int idx = tid; idx < 128 * DVS; idx += 256) S.S[idx >> 4][idx & 15] = 0.f;

    for (int n = 0; n < NCHUNK; n++) {
        int base = h * T_LEN + n * 64;
        if (tid < 64) S.gcs[tid] = ggcs[base + tid];
        for (int idx = tid; idx < 64 * 128; idx += 256) {
            int i = idx >> 7, d = idx & 127;
            size_t gidx = (size_t)(base + i) * DHEAD + d;
            S.w[i][d] = gw[gidx];
            S.q[i][d] = gq[gidx];
            S.k[i][d] = gk[gidx];
        }
        const float* ap = gattn + ((size_t)(h * 64 + n)) * 64 * 64;
        for (int idx = tid; idx < 4096; idx += 256) S.attn[idx >> 6][idx & 63] = ap[idx];
        for (int idx = tid; idx < 64 * DVS; idx += 256) {
            int i = idx >> 4, dv = idx & 15;
            S.u[i][dv] = gu[(size_t)(base + i) * DHEAD + dv0 + dv];
        }
        __syncthreads();
        if (tid < 64) S.ex[tid] = __expf(S.gcs[63] - S.gcs[tid]);

        int i = tid >> 2, dvb = (tid & 3) * 4;
        {
            float4 uv = *(const float4*)&S.u[i][dvb];
            float a0 = uv.x, a1 = uv.y, a2 = uv.z, a3 = uv.w;
            for (int d = 0; d < 128; d++) {
                float wv = S.w[i][d];
                float4 sv = *(const float4*)&S.S[d][dvb];
                a0 -= wv * sv.x; a1 -= wv * sv.y; a2 -= wv * sv.z; a3 -= wv * sv.w;
            }
            float4 r; r.x = a0; r.y = a1; r.z = a2; r.w = a3;
            *(float4*)&S.vn[i][dvb] = r;
        }
        __syncthreads();
        {
            float a0 = 0, a1 = 0, a2 = 0, a3 = 0;
            for (int d = 0; d < 128; d++) {
                float qv = S.q[i][d];
                float4 sv = *(const float4*)&S.S[d][dvb];
                a0 += qv * sv.x; a1 += qv * sv.y; a2 += qv * sv.z; a3 += qv * sv.w;
            }
            float eg = __expf(S.gcs[i]);
            a0 *= eg; a1 *= eg; a2 *= eg; a3 *= eg;
            for (int j = 0; j <= i; j++) {
                float av = S.attn[i][j];
                float4 vv = *(const float4*)&S.vn[j][dvb];
                a0 += av * vv.x; a1 += av * vv.y; a2 += av * vv.z; a3 += av * vv.w;
            }
            float4 r; r.x = a0; r.y = a1; r.z = a2; r.w = a3;
            *(float4*)(go + (size_t)(base + i) * DHEAD + dv0 + dvb) = r;
        }
        __syncthreads();
        {
            float gle = __expf(S.gcs[63]);
            #pragma unroll
            for (int r = 0; r < 2; r++) {
                int qi = tid + 256 * r;
                int d = qi >> 2, db = (qi & 3) * 4;
                float4 sv = *(const float4*)&S.S[d][db];
                float a0 = sv.x * gle, a1 = sv.y * gle, a2 = sv.z * gle, a3 = sv.w * gle;
                for (int ii = 0; ii < 64; ii++) {
                    float kk = S.k[ii][d] * S.ex[ii];
                    float4 vv = *(const float4*)&S.vn[ii][db];
                    a0 += kk * vv.x; a1 += kk * vv.y; a2 += kk * vv.z; a3 += kk * vv.w;
                }
                float4 w4; w4.x = a0; w4.y = a1; w4.z = a2; w4.w = a3;
                *(float4*)&S.S[d][db] = w4;
            }
        }
        __syncthreads();
    }
}

// ---------------- gated RMSNorm * silu(z) -> fp16 ----------------
__global__ void gated_out_kernel(const float* __restrict__ go, const float* __restrict__ qkvz,
                                 const float* __restrict__ onw, __half* __restrict__ oc16) {
    int h = blockIdx.x, t = blockIdx.y, d = threadIdx.x;
    __shared__ float shm[32];
    float v = go[((size_t)h * T_LEN + t) * DHEAD + d];
    float ss = block_reduce_sum(v * v, shm, d, 128);
    float inv = rsqrtf(ss / 128.f + 1e-5f);
    float z = qkvz[(size_t)t * QKVZ_N + MIX_N + h * 128 + d];
    float res = v * inv * onw[d] * silu_f(z);
    oc16[(size_t)t * DMODEL + h * 128 + d] = __float2half(res);
}

// ---------------- GLU -> fp16 ----------------
__global__ void glu_kernel(const float* __restrict__ gate, const float* __restrict__ up,
                           __half* __restrict__ gu16) {
    int i = blockIdx.x * blockDim.x + threadIdx.x;
    float v = silu_f(gate[i]) * up[i];
    gu16[i] = __float2half(v);
}

// ---------------- host launch ----------------
extern "C" void kernel_launch(void* const* d_in, const int* in_sizes, int n_in,
                              void* d_out, int out_size) {
    const float* x       = (const float*)d_in[0];
    const float* ln1_w   = (const float*)d_in[2];
    const float* qkvz_w  = (const float*)d_in[3];
    const float* ba_w    = (const float*)d_in[4];
    const float* conv_w  = (const float*)d_in[5];
    const float* A_log   = (const float*)d_in[6];
    const float* dt_bias = (const float*)d_in[7];
    const float* o_norm_w= (const float*)d_in[8];
    const float* out_w   = (const float*)d_in[9];
    const float* ln2_w   = (const float*)d_in[10];
    const float* gate_w  = (const float*)d_in[11];
    const float* up_w    = (const float*)d_in[12];
    const float* down_w  = (const float*)d_in[13];
    float* out = (float*)d_out;

    float *h, *qkvz, *ba, *qb, *kb, *vb, *beta, *gg, *gcs, *u, *w, *attn, *o, *x2, *up;
    cudaGetSymbolAddress((void**)&h,    g_h);
    cudaGetSymbolAddress((void**)&qkvz, g_qkvz);
    cudaGetSymbolAddress((void**)&ba,   g_ba);
    cudaGetSymbolAddress((void**)&qb,   g_qb);
    cudaGetSymbolAddress((void**)&kb,   g_kb);
    cudaGetSymbolAddress((void**)&vb,   g_vb);
    cudaGetSymbolAddress((void**)&beta, g_beta);
    cudaGetSymbolAddress((void**)&gg,   g_g);
    cudaGetSymbolAddress((void**)&gcs,  g_gcs);
    cudaGetSymbolAddress((void**)&u,    g_u);
    cudaGetSymbolAddress((void**)&w,    g_wb);
    cudaGetSymbolAddress((void**)&attn, g_attn);
    cudaGetSymbolAddress((void**)&o,    g_o);
    cudaGetSymbolAddress((void**)&x2,   g_x2);
    cudaGetSymbolAddress((void**)&up,   g_up);

    __half *h16, *oc16, *gu16, *w1, *wo, *wg, *wu, *wd;
    cudaGetSymbolAddress((void**)&h16,  b_h16);
    cudaGetSymbolAddress((void**)&oc16, b_oc16);
    cudaGetSymbolAddress((void**)&gu16, b_gu16);
    cudaGetSymbolAddress((void**)&w1,   b_w1);
    cudaGetSymbolAddress((void**)&wo,   b_wo);
    cudaGetSymbolAddress((void**)&wg,   b_wg);
    cudaGetSymbolAddress((void**)&wu,   b_wu);
    cudaGetSymbolAddress((void**)&wd,   b_wd);

    cudaFuncSetAttribute(prep_kernel, cudaFuncAttributeMaxDynamicSharedMemorySize, (int)sizeof(PrepShm));
    cudaFuncSetAttribute(scan_kernel, cudaFuncAttributeMaxDynamicSharedMemorySize, (int)sizeof(ScanShm));
    const int GSMEM = 3 * GSTAGE;  // 48KB
    cudaFuncSetAttribute(gemm_tc, cudaFuncAttributeMaxDynamicSharedMemorySize, GSMEM);

    // weight conversions
    cvt16<<<(QKVZ_N * DMODEL) / 1024, 256>>>(qkvz_w, w1, QKVZ_N * DMODEL);
    cvt16<<<(DMODEL * DMODEL) / 1024, 256>>>(out_w,  wo, DMODEL * DMODEL);
    cvt16<<<(MDIM * DMODEL) / 1024, 256>>>(gate_w, wg, MDIM * DMODEL);
    cvt16<<<(MDIM * DMODEL) / 1024, 256>>>(up_w,   wu, MDIM * DMODEL);
    cvt16<<<(DMODEL * MDIM) / 1024, 256>>>(down_w, wd, DMODEL * MDIM);

    // 1) h = rms(x, ln1) (+ fp16)
    rmsnorm_kernel<<<T_LEN, 256>>>(x, ln1_w, h, h16);
    // 2) qkvz = h @ qkvz_w^T ; ba = h @ ba_w^T
    gemm_tc<<<dim3(QKVZ_N / 128, T_LEN / 128), 256, GSMEM>>>(h16, w1, (const float*)0, qkvz, T_LEN, QKVZ_N, DMODEL);
    gemm_n32<<<T_LEN / 32, 256>>>(h, ba_w, ba, DMODEL);
    // 3) conv + silu + l2norm
    conv_kernel<<<dim3(48, T_LEN), 128>>>(qkvz, conv_w, qb, kb, vb);
    // 4) beta, g, gcs
    betag_kernel<<<(NHEAD * T_LEN + 255) / 256, 256>>>(ba, A_log, dt_bias, beta, gg);
    gcs_kernel<<<NHEAD * NCHUNK, 64>>>(gg, gcs);
    // 5) chunk prep
    prep_kernel<<<dim3(NCHUNK, NHEAD), 128, sizeof(PrepShm)>>>(kb, vb, qb, beta, gcs, u, w, attn);
    // 6) scan
    scan_kernel<<<dim3(NHEAD, DHEAD / DVS), 256, sizeof(ScanShm)>>>(qb, kb, w, u, attn, gcs, o);
    // 7) gated norm * silu(z) -> oc16
    gated_out_kernel<<<dim3(NHEAD, T_LEN), 128>>>(o, qkvz, o_norm_w, oc16);
    // 8) x2 = x + oc @ out_w^T
    gemm_tc<<<dim3(DMODEL / 128, T_LEN / 128), 256, GSMEM>>>(oc16, wo, x, x2, T_LEN, DMODEL, DMODEL);
    // 9) h2 = rms(x2, ln2)
    rmsnorm_kernel<<<T_LEN, 256>>>(x2, ln2_w, h, h16);
    // 10) gate, up GEMMs
    gemm_tc<<<dim3(MDIM / 128, T_LEN / 128), 256, GSMEM>>>(h16, wg, (const float*)0, qkvz, T_LEN, MDIM, DMODEL);
    gemm_tc<<<dim3(MDIM / 128, T_LEN / 128), 256, GSMEM>>>(h16, wu, (const float*)0, up, T_LEN, MDIM, DMODEL);
    // 11) gu = silu(gate) * up -> fp16
    glu_kernel<<<(T_LEN * MDIM) / 256, 256>>>(qkvz, up, gu16);
    // 12) out = x2 + gu @ down_w^T
    gemm_tc<<<dim3(DMODEL / 128, T_LEN / 128), 256, GSMEM>>>(gu16, wd, x2, out, T_LEN, DMODEL, MDIM);
}